// round 9
// baseline (speedup 1.0000x reference)
#include <cuda_runtime.h>
#include <cuda_bf16.h>
#include <math.h>

// Problem constants
#define B_   2
#define S_   2048
#define DM_  2048
#define NH_  32
#define NKV_ 8
#define DH_  64
#define BS_  (B_ * S_)          // 4096 rows
#define QKDIM_ (NH_ * DH_)      // 2048
#define KVDIM_ (NKV_ * DH_)     // 512

// Scratch (device globals: allocation-free rule)
__device__ float g_q [BS_ * QKDIM_];
__device__ float g_k [BS_ * KVDIM_];
__device__ float g_v [BS_ * KVDIM_];
__device__ float g_ao[BS_ * QKDIM_];

// ---------------------------------------------------------------------------
// Split-precision helpers: x ~= hi + lo, each bf16.
// ---------------------------------------------------------------------------
__device__ __forceinline__ void split_bf16(float x, __nv_bfloat16& h, __nv_bfloat16& l)
{
    h = __float2bfloat16(x);
    l = __float2bfloat16(x - __bfloat162float(h));
}

__device__ __forceinline__ unsigned pack2hi(float a, float b)   // bf16(a) low, bf16(b) high
{
    unsigned lo = __bfloat16_as_ushort(__float2bfloat16(a));
    unsigned hi = __bfloat16_as_ushort(__float2bfloat16(b));
    return lo | (hi << 16);
}
__device__ __forceinline__ unsigned pack2lo(float a, float b)   // residuals
{
    float ra = a - __bfloat162float(__float2bfloat16(a));
    float rb = b - __bfloat162float(__float2bfloat16(b));
    return pack2hi(ra, rb);
}

// mma.sync m16n8k16 row.col bf16 -> f32 accumulate (in-place)
__device__ __forceinline__ void mma16816(float c[4], const unsigned a[4], const unsigned b[2])
{
    asm volatile(
        "mma.sync.aligned.m16n8k16.row.col.f32.bf16.bf16.f32 "
        "{%0,%1,%2,%3}, {%4,%5,%6,%7}, {%8,%9}, {%0,%1,%2,%3};\n"
        : "+f"(c[0]), "+f"(c[1]), "+f"(c[2]), "+f"(c[3])
        : "r"(a[0]), "r"(a[1]), "r"(a[2]), "r"(a[3]), "r"(b[0]), "r"(b[1]));
}

// ---------------------------------------------------------------------------
// Tensor-core GEMM with split-bf16 (3 MMA products): C = A * op(B), fp32 I/O.
// Block tile 128x128x32, 8 warps (2 m x 4 n), warp tile 64x32.
// ---------------------------------------------------------------------------
#define TP 36

template <int TRANS_B>
__global__ __launch_bounds__(256)
void gemm_mma(const float* __restrict__ A, const float* __restrict__ Bm,
              float* __restrict__ C, int M, int N, int K)
{
    __shared__ __align__(16) __nv_bfloat16 Ah[128][TP];
    __shared__ __align__(16) __nv_bfloat16 Al[128][TP];
    __shared__ __align__(16) __nv_bfloat16 Bh[128][TP];
    __shared__ __align__(16) __nv_bfloat16 Bl[128][TP];

    const int tid  = threadIdx.x;
    const int m0   = blockIdx.y * 128;
    const int n0   = blockIdx.x * 128;
    const int warp = tid >> 5;
    const int lane = tid & 31;
    const int wm   = (warp & 1) * 64;
    const int wn   = (warp >> 1) * 32;
    const int g    = lane >> 2;
    const int tg   = lane & 3;

    float acc[4][4][4];
    #pragma unroll
    for (int i = 0; i < 4; i++)
        #pragma unroll
        for (int j = 0; j < 4; j++)
            #pragma unroll
            for (int r = 0; r < 4; r++) acc[i][j][r] = 0.f;

    for (int k0 = 0; k0 < K; k0 += 32) {
        #pragma unroll
        for (int l = 0; l < 4; l++) {
            int idx = tid + l * 256;
            int r = idx >> 3;
            int c = (idx & 7) * 4;
            float4 v = *(const float4*)(A + (size_t)(m0 + r) * K + k0 + c);
            split_bf16(v.x, Ah[r][c + 0], Al[r][c + 0]);
            split_bf16(v.y, Ah[r][c + 1], Al[r][c + 1]);
            split_bf16(v.z, Ah[r][c + 2], Al[r][c + 2]);
            split_bf16(v.w, Ah[r][c + 3], Al[r][c + 3]);
        }
        if (TRANS_B) {
            #pragma unroll
            for (int l = 0; l < 4; l++) {
                int idx = tid + l * 256;
                int r = idx >> 3;
                int c = (idx & 7) * 4;
                float4 v = *(const float4*)(Bm + (size_t)(n0 + r) * K + k0 + c);
                split_bf16(v.x, Bh[r][c + 0], Bl[r][c + 0]);
                split_bf16(v.y, Bh[r][c + 1], Bl[r][c + 1]);
                split_bf16(v.z, Bh[r][c + 2], Bl[r][c + 2]);
                split_bf16(v.w, Bh[r][c + 3], Bl[r][c + 3]);
            }
        } else {
            #pragma unroll
            for (int l = 0; l < 4; l++) {
                int idx = tid + l * 256;
                int r = idx >> 5;
                int c = (idx & 31) * 4;
                float4 v = *(const float4*)(Bm + (size_t)(k0 + r) * N + n0 + c);
                split_bf16(v.x, Bh[c + 0][r], Bl[c + 0][r]);
                split_bf16(v.y, Bh[c + 1][r], Bl[c + 1][r]);
                split_bf16(v.z, Bh[c + 2][r], Bl[c + 2][r]);
                split_bf16(v.w, Bh[c + 3][r], Bl[c + 3][r]);
            }
        }
        __syncthreads();

        #pragma unroll
        for (int kc = 0; kc < 32; kc += 16) {
            unsigned ah[4][4], al[4][4], bh[4][2], bl[4][2];
            #pragma unroll
            for (int mf = 0; mf < 4; mf++) {
                int r = wm + mf * 16 + g;
                ah[mf][0] = *(const unsigned*)&Ah[r    ][kc + tg * 2    ];
                ah[mf][1] = *(const unsigned*)&Ah[r + 8][kc + tg * 2    ];
                ah[mf][2] = *(const unsigned*)&Ah[r    ][kc + tg * 2 + 8];
                ah[mf][3] = *(const unsigned*)&Ah[r + 8][kc + tg * 2 + 8];
                al[mf][0] = *(const unsigned*)&Al[r    ][kc + tg * 2    ];
                al[mf][1] = *(const unsigned*)&Al[r + 8][kc + tg * 2    ];
                al[mf][2] = *(const unsigned*)&Al[r    ][kc + tg * 2 + 8];
                al[mf][3] = *(const unsigned*)&Al[r + 8][kc + tg * 2 + 8];
            }
            #pragma unroll
            for (int nf = 0; nf < 4; nf++) {
                int r = wn + nf * 8 + g;
                bh[nf][0] = *(const unsigned*)&Bh[r][kc + tg * 2    ];
                bh[nf][1] = *(const unsigned*)&Bh[r][kc + tg * 2 + 8];
                bl[nf][0] = *(const unsigned*)&Bl[r][kc + tg * 2    ];
                bl[nf][1] = *(const unsigned*)&Bl[r][kc + tg * 2 + 8];
            }
            #pragma unroll
            for (int mf = 0; mf < 4; mf++)
                #pragma unroll
                for (int nf = 0; nf < 4; nf++) {
                    mma16816(acc[mf][nf], ah[mf], bh[nf]);
                    mma16816(acc[mf][nf], ah[mf], bl[nf]);
                    mma16816(acc[mf][nf], al[mf], bh[nf]);
                }
        }
        __syncthreads();
    }

    #pragma unroll
    for (int mf = 0; mf < 4; mf++)
        #pragma unroll
        for (int nf = 0; nf < 4; nf++) {
            int r = m0 + wm + mf * 16 + g;
            int c = n0 + wn + nf * 8 + tg * 2;
            *(float2*)&C[(size_t)r * N + c]       = make_float2(acc[mf][nf][0], acc[mf][nf][1]);
            *(float2*)&C[(size_t)(r + 8) * N + c] = make_float2(acc[mf][nf][2], acc[mf][nf][3]);
        }
}

// ---------------------------------------------------------------------------
// Flash attention via tensor cores, causal, GQA, split-bf16 (3-product) MMAs.
// One block = 64 queries x one (batch, head). 128 threads = 4 warps.
// S C-fragments are reused directly as P A-fragments (FA2 identity).
// smem pitch 72 bf16 => fragment LDS bank = 4g+tg (conflict-free).
// ---------------------------------------------------------------------------
#define FP 72
#define FA_ARR (64 * FP)                       // 4608 bf16 elems per array
#define FA_SMEM (6 * FA_ARR * 2)               // 55296 bytes

__global__ __launch_bounds__(128)
void flash_mma(const float* __restrict__ Q, const float* __restrict__ K,
               const float* __restrict__ V, float* __restrict__ O)
{
    extern __shared__ __align__(16) __nv_bfloat16 smem[];
    __nv_bfloat16* sQh = smem;
    __nv_bfloat16* sQl = smem + 1 * FA_ARR;
    __nv_bfloat16* sKh = smem + 2 * FA_ARR;
    __nv_bfloat16* sKl = smem + 3 * FA_ARR;
    __nv_bfloat16* sVh = smem + 4 * FA_ARR;    // transposed: [d][key]
    __nv_bfloat16* sVl = smem + 5 * FA_ARR;

    const int qb   = blockIdx.x;
    const int head = blockIdx.y;
    const int b    = blockIdx.z;
    const int kvh  = head >> 2;
    const int tid  = threadIdx.x;
    const int warp = tid >> 5;
    const int lane = tid & 31;
    const int g    = lane >> 2;
    const int tg   = lane & 3;

    // ---- load Q tile (64x64), split hi/lo ----
    const float* Qb = Q + (size_t)(b * S_ + qb * 64) * QKDIM_ + head * DH_;
    for (int idx = tid; idx < 1024; idx += 128) {
        int r = idx >> 4, c = (idx & 15) * 4;
        float4 v = *(const float4*)(Qb + (size_t)r * QKDIM_ + c);
        split_bf16(v.x, sQh[r * FP + c + 0], sQl[r * FP + c + 0]);
        split_bf16(v.y, sQh[r * FP + c + 1], sQl[r * FP + c + 1]);
        split_bf16(v.z, sQh[r * FP + c + 2], sQl[r * FP + c + 2]);
        split_bf16(v.w, sQh[r * FP + c + 3], sQl[r * FP + c + 3]);
    }

    float m0 = -INFINITY, m1 = -INFINITY, l0 = 0.f, l1 = 0.f;
    float oacc[8][4];
    #pragma unroll
    for (int nf = 0; nf < 8; nf++)
        #pragma unroll
        for (int e = 0; e < 4; e++) oacc[nf][e] = 0.f;

    const float scale = 0.125f;                 // 1/sqrt(64)
    const float LOG2E = 1.44269504f;
    const int qrow0 = qb * 64 + warp * 16 + g;  // global row for frag row g
    const int nkb = qb + 1;

    for (int kb = 0; kb < nkb; kb++) {
        __syncthreads();   // previous iteration done reading sK/sV (also covers Q store)
        // ---- load K (row-major [key][d]) and V (transposed [d][key]) ----
        const float* Kb = K + (size_t)(b * S_ + kb * 64) * KVDIM_ + kvh * DH_;
        const float* Vb = V + (size_t)(b * S_ + kb * 64) * KVDIM_ + kvh * DH_;
        for (int idx = tid; idx < 1024; idx += 128) {
            int r = idx >> 4, c = (idx & 15) * 4;
            float4 v = *(const float4*)(Kb + (size_t)r * KVDIM_ + c);
            split_bf16(v.x, sKh[r * FP + c + 0], sKl[r * FP + c + 0]);
            split_bf16(v.y, sKh[r * FP + c + 1], sKl[r * FP + c + 1]);
            split_bf16(v.z, sKh[r * FP + c + 2], sKl[r * FP + c + 2]);
            split_bf16(v.w, sKh[r * FP + c + 3], sKl[r * FP + c + 3]);
        }
        for (int idx = tid; idx < 4096; idx += 128) {
            int key = idx >> 6, d = idx & 63;      // consecutive tid -> consecutive d (coalesced)
            float x = Vb[(size_t)key * KVDIM_ + d];
            split_bf16(x, sVh[d * FP + key], sVl[d * FP + key]);
        }
        __syncthreads();

        // ---- S = Q K^T (split, 3 products) ----
        float sc[8][4];
        #pragma unroll
        for (int nf = 0; nf < 8; nf++)
            #pragma unroll
            for (int e = 0; e < 4; e++) sc[nf][e] = 0.f;

        #pragma unroll
        for (int kc = 0; kc < 4; kc++) {
            const int r0 = warp * 16 + g;
            const int kk = kc * 16 + tg * 2;
            unsigned qh[4], ql[4];
            qh[0] = *(const unsigned*)&sQh[(r0    ) * FP + kk    ];
            qh[1] = *(const unsigned*)&sQh[(r0 + 8) * FP + kk    ];
            qh[2] = *(const unsigned*)&sQh[(r0    ) * FP + kk + 8];
            qh[3] = *(const unsigned*)&sQh[(r0 + 8) * FP + kk + 8];
            ql[0] = *(const unsigned*)&sQl[(r0    ) * FP + kk    ];
            ql[1] = *(const unsigned*)&sQl[(r0 + 8) * FP + kk    ];
            ql[2] = *(const unsigned*)&sQl[(r0    ) * FP + kk + 8];
            ql[3] = *(const unsigned*)&sQl[(r0 + 8) * FP + kk + 8];
            #pragma unroll
            for (int nf = 0; nf < 8; nf++) {
                int n = nf * 8 + g;
                unsigned bh[2], bl[2];
                bh[0] = *(const unsigned*)&sKh[n * FP + kk    ];
                bh[1] = *(const unsigned*)&sKh[n * FP + kk + 8];
                bl[0] = *(const unsigned*)&sKl[n * FP + kk    ];
                bl[1] = *(const unsigned*)&sKl[n * FP + kk + 8];
                mma16816(sc[nf], qh, bh);
                mma16816(sc[nf], qh, bl);
                mma16816(sc[nf], ql, bh);
            }
        }

        // ---- scale, causal mask, row stats ----
        const bool diag = (kb == qb);
        float rm0 = -1e30f, rm1 = -1e30f;
        #pragma unroll
        for (int nf = 0; nf < 8; nf++) {
            #pragma unroll
            for (int e = 0; e < 2; e++) {
                int kg = kb * 64 + nf * 8 + tg * 2 + e;
                float v0 = sc[nf][e] * scale;
                if (diag && kg > qrow0) v0 = -1e30f;
                sc[nf][e] = v0;
                rm0 = fmaxf(rm0, v0);
                float v1 = sc[nf][e + 2] * scale;
                if (diag && kg > qrow0 + 8) v1 = -1e30f;
                sc[nf][e + 2] = v1;
                rm1 = fmaxf(rm1, v1);
            }
        }
        rm0 = fmaxf(rm0, __shfl_xor_sync(0xffffffffu, rm0, 1));
        rm0 = fmaxf(rm0, __shfl_xor_sync(0xffffffffu, rm0, 2));
        rm1 = fmaxf(rm1, __shfl_xor_sync(0xffffffffu, rm1, 1));
        rm1 = fmaxf(rm1, __shfl_xor_sync(0xffffffffu, rm1, 2));

        const float mn0 = fmaxf(m0, rm0);
        const float mn1 = fmaxf(m1, rm1);
        const float a0 = exp2f((m0 - mn0) * LOG2E);
        const float a1 = exp2f((m1 - mn1) * LOG2E);
        m0 = mn0; m1 = mn1;
        l0 *= a0;  l1 *= a1;
        #pragma unroll
        for (int nf = 0; nf < 8; nf++) {
            oacc[nf][0] *= a0; oacc[nf][1] *= a0;
            oacc[nf][2] *= a1; oacc[nf][3] *= a1;
        }

        // ---- P = exp(S - m), row sums ----
        float rs0 = 0.f, rs1 = 0.f;
        #pragma unroll
        for (int nf = 0; nf < 8; nf++) {
            float p0 = exp2f((sc[nf][0] - mn0) * LOG2E);
            float p1 = exp2f((sc[nf][1] - mn0) * LOG2E);
            float p2 = exp2f((sc[nf][2] - mn1) * LOG2E);
            float p3 = exp2f((sc[nf][3] - mn1) * LOG2E);
            sc[nf][0] = p0; sc[nf][1] = p1; sc[nf][2] = p2; sc[nf][3] = p3;
            rs0 += p0 + p1; rs1 += p2 + p3;
        }
        rs0 += __shfl_xor_sync(0xffffffffu, rs0, 1);
        rs0 += __shfl_xor_sync(0xffffffffu, rs0, 2);
        rs1 += __shfl_xor_sync(0xffffffffu, rs1, 1);
        rs1 += __shfl_xor_sync(0xffffffffu, rs1, 2);
        l0 += rs0; l1 += rs1;

        // ---- pack P into split A-fragments (register-only handoff) ----
        unsigned ph[8][2], pl[8][2];
        #pragma unroll
        for (int nf = 0; nf < 8; nf++) {
            ph[nf][0] = pack2hi(sc[nf][0], sc[nf][1]);   // row g pair
            ph[nf][1] = pack2hi(sc[nf][2], sc[nf][3]);   // row g+8 pair
            pl[nf][0] = pack2lo(sc[nf][0], sc[nf][1]);
            pl[nf][1] = pack2lo(sc[nf][2], sc[nf][3]);
        }

        // ---- O += P V (split, 3 products); k-dim = keys ----
        #pragma unroll
        for (int kc = 0; kc < 4; kc++) {
            unsigned ah[4] = { ph[2*kc][0], ph[2*kc][1], ph[2*kc+1][0], ph[2*kc+1][1] };
            unsigned al[4] = { pl[2*kc][0], pl[2*kc][1], pl[2*kc+1][0], pl[2*kc+1][1] };
            const int kk = kc * 16 + tg * 2;
            #pragma unroll
            for (int nf = 0; nf < 8; nf++) {
                int n = nf * 8 + g;                       // dhead column
                unsigned vh[2], vl[2];
                vh[0] = *(const unsigned*)&sVh[n * FP + kk    ];
                vh[1] = *(const unsigned*)&sVh[n * FP + kk + 8];
                vl[0] = *(const unsigned*)&sVl[n * FP + kk    ];
                vl[1] = *(const unsigned*)&sVl[n * FP + kk + 8];
                mma16816(oacc[nf], ah, vh);
                mma16816(oacc[nf], ah, vl);
                mma16816(oacc[nf], al, vh);
            }
        }
    }

    // ---- normalize + store ----
    const float inv0 = 1.0f / l0;
    const float inv1 = 1.0f / l1;
    float* Ob = O + (size_t)(b * S_ + qb * 64) * QKDIM_ + head * DH_;
    const int r0 = warp * 16 + g;
    #pragma unroll
    for (int nf = 0; nf < 8; nf++) {
        int c = nf * 8 + tg * 2;
        *(float2*)&Ob[(size_t)(r0    ) * QKDIM_ + c] = make_float2(oacc[nf][0] * inv0, oacc[nf][1] * inv0);
        *(float2*)&Ob[(size_t)(r0 + 8) * QKDIM_ + c] = make_float2(oacc[nf][2] * inv1, oacc[nf][3] * inv1);
    }
}

// ---------------------------------------------------------------------------
extern "C" void kernel_launch(void* const* d_in, const int* in_sizes, int n_in,
                              void* d_out, int out_size)
{
    const float* X  = (const float*)d_in[0];
    const float* WQ = (const float*)d_in[1];
    const float* WK = (const float*)d_in[2];
    const float* WV = (const float*)d_in[3];
    const float* WO = (const float*)d_in[4];
    float* out = (float*)d_out;

    float *q, *k, *v, *ao;
    cudaGetSymbolAddress((void**)&q,  g_q);
    cudaGetSymbolAddress((void**)&k,  g_k);
    cudaGetSymbolAddress((void**)&v,  g_v);
    cudaGetSymbolAddress((void**)&ao, g_ao);

    // QKV projections (NT GEMMs, tensor cores)
    gemm_mma<1><<<dim3(QKDIM_ / 128, BS_ / 128), 256>>>(X, WQ, q,  BS_, QKDIM_, DM_);
    gemm_mma<1><<<dim3(KVDIM_ / 128, BS_ / 128), 256>>>(X, WK, k,  BS_, KVDIM_, DM_);
    gemm_mma<1><<<dim3(KVDIM_ / 128, BS_ / 128), 256>>>(X, WV, v,  BS_, KVDIM_, DM_);

    // Flash attention (tensor cores, split-bf16)
    cudaFuncSetAttribute(flash_mma, cudaFuncAttributeMaxDynamicSharedMemorySize, FA_SMEM);
    flash_mma<<<dim3(S_ / 64, NH_, B_), 128, FA_SMEM>>>(q, k, v, ao);

    // Output projection (NN GEMM, tensor cores)
    gemm_mma<0><<<dim3(DM_ / 128, BS_ / 128), 256>>>(ao, WO, out, BS_, DM_, DM_);
}

// round 12
// speedup vs baseline: 1.2912x; 1.2912x over previous
#include <cuda_runtime.h>
#include <cuda_bf16.h>
#include <math.h>

// Problem constants
#define B_   2
#define S_   2048
#define DM_  2048
#define NH_  32
#define NKV_ 8
#define DH_  64
#define BS_  (B_ * S_)          // 4096 rows
#define QKDIM_ (NH_ * DH_)      // 2048
#define KVDIM_ (NKV_ * DH_)     // 512

typedef __nv_bfloat16 bf16;

// ---------------------------------------------------------------------------
// Scratch (device globals). Everything between kernels is split bf16 hi/lo.
// ---------------------------------------------------------------------------
__device__ bf16 sXh [BS_ * DM_],     sXl [BS_ * DM_];       // residual
__device__ bf16 sWQh[QKDIM_ * DM_],  sWQl[QKDIM_ * DM_];    // [N][K]
__device__ bf16 sWKh[KVDIM_ * DM_],  sWKl[KVDIM_ * DM_];
__device__ bf16 sWVh[KVDIM_ * DM_],  sWVl[KVDIM_ * DM_];
__device__ bf16 sWOh[DM_ * QKDIM_],  sWOl[DM_ * QKDIM_];    // transposed: [n=dmodel][k=headcol]
__device__ bf16 sqh [BS_ * QKDIM_],  sql [BS_ * QKDIM_];
__device__ bf16 skh [BS_ * KVDIM_],  skl [BS_ * KVDIM_];
__device__ bf16 svh [BS_ * KVDIM_],  svl [BS_ * KVDIM_];
__device__ bf16 saoh[BS_ * QKDIM_],  saol[BS_ * QKDIM_];

// ---------------------------------------------------------------------------
// Split helpers
// ---------------------------------------------------------------------------
__device__ __forceinline__ unsigned pack2hi(float a, float b)
{
    unsigned lo = __bfloat16_as_ushort(__float2bfloat16(a));
    unsigned hi = __bfloat16_as_ushort(__float2bfloat16(b));
    return lo | (hi << 16);
}
__device__ __forceinline__ unsigned pack2lo(float a, float b)
{
    float ra = a - __bfloat162float(__float2bfloat16(a));
    float rb = b - __bfloat162float(__float2bfloat16(b));
    return pack2hi(ra, rb);
}

// mma.sync m16n8k16 row.col bf16 -> f32 accumulate (in-place)
__device__ __forceinline__ void mma16816(float c[4], const unsigned a[4], const unsigned b[2])
{
    asm volatile(
        "mma.sync.aligned.m16n8k16.row.col.f32.bf16.bf16.f32 "
        "{%0,%1,%2,%3}, {%4,%5,%6,%7}, {%8,%9}, {%0,%1,%2,%3};\n"
        : "+f"(c[0]), "+f"(c[1]), "+f"(c[2]), "+f"(c[3])
        : "r"(a[0]), "r"(a[1]), "r"(a[2]), "r"(a[3]), "r"(b[0]), "r"(b[1]));
}

// cp.async 16B
__device__ __forceinline__ void cpa16(void* s, const void* g)
{
    unsigned sa = (unsigned)__cvta_generic_to_shared(s);
    asm volatile("cp.async.cg.shared.global [%0], [%1], 16;\n" :: "r"(sa), "l"(g) : "memory");
}
#define CP_COMMIT() asm volatile("cp.async.commit_group;\n" ::: "memory")
#define CP_WAIT1()  asm volatile("cp.async.wait_group 1;\n" ::: "memory")
#define CP_WAIT0()  asm volatile("cp.async.wait_group 0;\n" ::: "memory")

// ---------------------------------------------------------------------------
// Conversion kernels (run every call; bandwidth-bound, ~40us total)
// ---------------------------------------------------------------------------
__global__ void k_split(const float4* __restrict__ in, uint2* __restrict__ h,
                        uint2* __restrict__ l, int n4)
{
    int i = blockIdx.x * blockDim.x + threadIdx.x;
    if (i < n4) {
        float4 v = in[i];
        uint2 hh, ll;
        hh.x = pack2hi(v.x, v.y); hh.y = pack2hi(v.z, v.w);
        ll.x = pack2lo(v.x, v.y); ll.y = pack2lo(v.z, v.w);
        h[i] = hh; l[i] = ll;
    }
}

// split + transpose: in [K=2048][N=2048] fp32 -> th/tl [N][K] bf16
__global__ void k_split_t(const float* __restrict__ in, bf16* __restrict__ th,
                          bf16* __restrict__ tl)
{
    __shared__ float t[32][33];
    const int tx = threadIdx.x, ty = threadIdx.y;
    const int kin0 = blockIdx.y * 32;
    const int nin0 = blockIdx.x * 32;
    for (int j = ty; j < 32; j += 8)
        t[j][tx] = in[(size_t)(kin0 + j) * DM_ + nin0 + tx];   // t[k'][n'] = in[k][n]
    __syncthreads();
    for (int j = ty; j < 32; j += 8) {
        float v = t[tx][j];                                    // = in[kin0+tx][nin0+j]
        size_t o = (size_t)(nin0 + j) * DM_ + kin0 + tx;       // th[n][k]
        bf16 hv = __float2bfloat16(v);
        th[o] = hv;
        tl[o] = __float2bfloat16(v - __bfloat162float(hv));
    }
}

// ---------------------------------------------------------------------------
// NT GEMM, pre-split bf16 operands, cp.async double-buffered.
// C[M,N] = A[M,K] * B[N,K]^T (both hi+lo, 3-product split accumulate).
// Block 128x128x32, 8 warps (2m x 4n). K is always 2048 here.
// WRITE_SPLIT=1: write Ch/Cl bf16; else write fp32 C.
// ---------------------------------------------------------------------------
#define GP 40                         // smem pitch in bf16 (80B rows, 16B-aligned)
#define GSTAGE (128 * GP)             // elems per array per stage

template <int WRITE_SPLIT>
__global__ __launch_bounds__(256)
void gemm_nt(const bf16* __restrict__ Agh, const bf16* __restrict__ Agl,
             const bf16* __restrict__ Bgh, const bf16* __restrict__ Bgl,
             float* __restrict__ C, bf16* __restrict__ Ch, bf16* __restrict__ Cl,
             int M, int N, int K)
{
    extern __shared__ __align__(16) bf16 sm[];
    const int tid  = threadIdx.x;
    const int m0   = blockIdx.y * 128;
    const int n0   = blockIdx.x * 128;
    const int warp = tid >> 5;
    const int lane = tid & 31;
    const int wm   = (warp & 1) * 64;
    const int wn   = (warp >> 1) * 32;
    const int g    = lane >> 2;
    const int tg   = lane & 3;

    float acc[4][4][4];
    #pragma unroll
    for (int i = 0; i < 4; i++)
        #pragma unroll
        for (int j = 0; j < 4; j++)
            #pragma unroll
            for (int r = 0; r < 4; r++) acc[i][j][r] = 0.f;

    const int T = K / 32;

    auto load_stage = [&](int st, int k0) {
        bf16* sAh = sm + (st * 4 + 0) * GSTAGE;
        bf16* sAl = sm + (st * 4 + 1) * GSTAGE;
        bf16* sBh = sm + (st * 4 + 2) * GSTAGE;
        bf16* sBl = sm + (st * 4 + 3) * GSTAGE;
        #pragma unroll
        for (int l = 0; l < 2; l++) {
            int idx = tid + l * 256;          // 0..511
            int row = idx >> 2, ch = idx & 3;
            int so  = row * GP + ch * 8;
            size_t ga = (size_t)(m0 + row) * K + k0 + ch * 8;
            size_t gb = (size_t)(n0 + row) * K + k0 + ch * 8;
            cpa16(sAh + so, Agh + ga);
            cpa16(sAl + so, Agl + ga);
            cpa16(sBh + so, Bgh + gb);
            cpa16(sBl + so, Bgl + gb);
        }
    };

    load_stage(0, 0);
    CP_COMMIT();

    for (int it = 0; it < T; it++) {
        if (it + 1 < T) {
            load_stage((it + 1) & 1, (it + 1) * 32);
            CP_COMMIT();
            CP_WAIT1();
        } else {
            CP_WAIT0();
        }
        __syncthreads();

        const int st = it & 1;
        const bf16* sAh = sm + (st * 4 + 0) * GSTAGE;
        const bf16* sAl = sm + (st * 4 + 1) * GSTAGE;
        const bf16* sBh = sm + (st * 4 + 2) * GSTAGE;
        const bf16* sBl = sm + (st * 4 + 3) * GSTAGE;

        #pragma unroll
        for (int kc = 0; kc < 32; kc += 16) {
            unsigned ah[4][4], al[4][4], bh[4][2], bl[4][2];
            #pragma unroll
            for (int mf = 0; mf < 4; mf++) {
                int r = wm + mf * 16 + g;
                ah[mf][0] = *(const unsigned*)&sAh[(r    ) * GP + kc + tg * 2    ];
                ah[mf][1] = *(const unsigned*)&sAh[(r + 8) * GP + kc + tg * 2    ];
                ah[mf][2] = *(const unsigned*)&sAh[(r    ) * GP + kc + tg * 2 + 8];
                ah[mf][3] = *(const unsigned*)&sAh[(r + 8) * GP + kc + tg * 2 + 8];
                al[mf][0] = *(const unsigned*)&sAl[(r    ) * GP + kc + tg * 2    ];
                al[mf][1] = *(const unsigned*)&sAl[(r + 8) * GP + kc + tg * 2    ];
                al[mf][2] = *(const unsigned*)&sAl[(r    ) * GP + kc + tg * 2 + 8];
                al[mf][3] = *(const unsigned*)&sAl[(r + 8) * GP + kc + tg * 2 + 8];
            }
            #pragma unroll
            for (int nf = 0; nf < 4; nf++) {
                int r = wn + nf * 8 + g;
                bh[nf][0] = *(const unsigned*)&sBh[r * GP + kc + tg * 2    ];
                bh[nf][1] = *(const unsigned*)&sBh[r * GP + kc + tg * 2 + 8];
                bl[nf][0] = *(const unsigned*)&sBl[r * GP + kc + tg * 2    ];
                bl[nf][1] = *(const unsigned*)&sBl[r * GP + kc + tg * 2 + 8];
            }
            #pragma unroll
            for (int mf = 0; mf < 4; mf++)
                #pragma unroll
                for (int nf = 0; nf < 4; nf++) {
                    mma16816(acc[mf][nf], ah[mf], bh[nf]);
                    mma16816(acc[mf][nf], ah[mf], bl[nf]);
                    mma16816(acc[mf][nf], al[mf], bh[nf]);
                }
        }
        __syncthreads();
    }

    #pragma unroll
    for (int mf = 0; mf < 4; mf++)
        #pragma unroll
        for (int nf = 0; nf < 4; nf++) {
            int r = m0 + wm + mf * 16 + g;
            int c = n0 + wn + nf * 8 + tg * 2;
            if (WRITE_SPLIT) {
                *(unsigned*)&Ch[(size_t)r * N + c]       = pack2hi(acc[mf][nf][0], acc[mf][nf][1]);
                *(unsigned*)&Cl[(size_t)r * N + c]       = pack2lo(acc[mf][nf][0], acc[mf][nf][1]);
                *(unsigned*)&Ch[(size_t)(r + 8) * N + c] = pack2hi(acc[mf][nf][2], acc[mf][nf][3]);
                *(unsigned*)&Cl[(size_t)(r + 8) * N + c] = pack2lo(acc[mf][nf][2], acc[mf][nf][3]);
            } else {
                *(float2*)&C[(size_t)r * N + c]       = make_float2(acc[mf][nf][0], acc[mf][nf][1]);
                *(float2*)&C[(size_t)(r + 8) * N + c] = make_float2(acc[mf][nf][2], acc[mf][nf][3]);
            }
        }
}

// ---------------------------------------------------------------------------
// Flash attention, tensor cores, split-bf16 inputs from gmem (no conversion).
// One block = 64 queries x one (batch, head). 128 threads = 4 warps.
// Writes split bf16 output for the O-projection.
// ---------------------------------------------------------------------------
#define FP 72
#define FA_ARR (64 * FP)
#define FA_SMEM (6 * FA_ARR * 2)        // 55296 bytes

__global__ __launch_bounds__(128)
void flash_mma(const bf16* __restrict__ Qh, const bf16* __restrict__ Ql,
               const bf16* __restrict__ Kh, const bf16* __restrict__ Kl,
               const bf16* __restrict__ Vh, const bf16* __restrict__ Vl,
               bf16* __restrict__ Oh, bf16* __restrict__ Ol)
{
    extern __shared__ __align__(16) bf16 smem[];
    bf16* sQh = smem;
    bf16* sQl = smem + 1 * FA_ARR;
    bf16* sKh = smem + 2 * FA_ARR;
    bf16* sKl = smem + 3 * FA_ARR;
    bf16* sVh = smem + 4 * FA_ARR;      // transposed: [d][key]
    bf16* sVl = smem + 5 * FA_ARR;

    const int qb   = blockIdx.x;
    const int head = blockIdx.y;
    const int b    = blockIdx.z;
    const int kvh  = head >> 2;
    const int tid  = threadIdx.x;
    const int warp = tid >> 5;
    const int lane = tid & 31;
    const int g    = lane >> 2;
    const int tg   = lane & 3;

    // ---- load Q tile (64x64 bf16 pairs), plain vector copies ----
    {
        const bf16* qhb = Qh + (size_t)(b * S_ + qb * 64) * QKDIM_ + head * DH_;
        const bf16* qlb = Ql + (size_t)(b * S_ + qb * 64) * QKDIM_ + head * DH_;
        for (int idx = tid; idx < 512; idx += 128) {       // 64 rows x 8 chunks
            int r = idx >> 3, ch = (idx & 7) * 8;
            *(uint4*)&sQh[r * FP + ch] = *(const uint4*)(qhb + (size_t)r * QKDIM_ + ch);
            *(uint4*)&sQl[r * FP + ch] = *(const uint4*)(qlb + (size_t)r * QKDIM_ + ch);
        }
    }

    float m0 = -INFINITY, m1 = -INFINITY, l0 = 0.f, l1 = 0.f;
    float oacc[8][4];
    #pragma unroll
    for (int nf = 0; nf < 8; nf++)
        #pragma unroll
        for (int e = 0; e < 4; e++) oacc[nf][e] = 0.f;

    const float scale = 0.125f;
    const float LOG2E = 1.44269504f;
    const int qrow0 = qb * 64 + warp * 16 + g;
    const int nkb = qb + 1;

    for (int kb = 0; kb < nkb; kb++) {
        __syncthreads();
        const bf16* khb = Kh + (size_t)(b * S_ + kb * 64) * KVDIM_ + kvh * DH_;
        const bf16* klb = Kl + (size_t)(b * S_ + kb * 64) * KVDIM_ + kvh * DH_;
        for (int idx = tid; idx < 512; idx += 128) {
            int r = idx >> 3, ch = (idx & 7) * 8;
            *(uint4*)&sKh[r * FP + ch] = *(const uint4*)(khb + (size_t)r * KVDIM_ + ch);
            *(uint4*)&sKl[r * FP + ch] = *(const uint4*)(klb + (size_t)r * KVDIM_ + ch);
        }
        // V transposed into smem [d][key]; coalesced 32-bit gmem reads
        const bf16* vhb = Vh + (size_t)(b * S_ + kb * 64) * KVDIM_ + kvh * DH_;
        const bf16* vlb = Vl + (size_t)(b * S_ + kb * 64) * KVDIM_ + kvh * DH_;
        for (int idx = tid; idx < 2048; idx += 128) {      // 64 keys x 32 words
            int key = idx >> 5, dw = (idx & 31) * 2;
            unsigned wh = *(const unsigned*)(vhb + (size_t)key * KVDIM_ + dw);
            unsigned wl = *(const unsigned*)(vlb + (size_t)key * KVDIM_ + dw);
            sVh[(dw    ) * FP + key] = __ushort_as_bfloat16((unsigned short)(wh & 0xffff));
            sVh[(dw + 1) * FP + key] = __ushort_as_bfloat16((unsigned short)(wh >> 16));
            sVl[(dw    ) * FP + key] = __ushort_as_bfloat16((unsigned short)(wl & 0xffff));
            sVl[(dw + 1) * FP + key] = __ushort_as_bfloat16((unsigned short)(wl >> 16));
        }
        __syncthreads();

        // ---- S = Q K^T (split, 3 products) ----
        float sc[8][4];
        #pragma unroll
        for (int nf = 0; nf < 8; nf++)
            #pragma unroll
            for (int e = 0; e < 4; e++) sc[nf][e] = 0.f;

        #pragma unroll
        for (int kc = 0; kc < 4; kc++) {
            const int r0 = warp * 16 + g;
            const int kk = kc * 16 + tg * 2;
            unsigned qh[4], ql[4];
            qh[0] = *(const unsigned*)&sQh[(r0    ) * FP + kk    ];
            qh[1] = *(const unsigned*)&sQh[(r0 + 8) * FP + kk    ];
            qh[2] = *(const unsigned*)&sQh[(r0    ) * FP + kk + 8];
            qh[3] = *(const unsigned*)&sQh[(r0 + 8) * FP + kk + 8];
            ql[0] = *(const unsigned*)&sQl[(r0    ) * FP + kk    ];
            ql[1] = *(const unsigned*)&sQl[(r0 + 8) * FP + kk    ];
            ql[2] = *(const unsigned*)&sQl[(r0    ) * FP + kk + 8];
            ql[3] = *(const unsigned*)&sQl[(r0 + 8) * FP + kk + 8];
            #pragma unroll
            for (int nf = 0; nf < 8; nf++) {
                int n = nf * 8 + g;
                unsigned bh[2], bl[2];
                bh[0] = *(const unsigned*)&sKh[n * FP + kk    ];
                bh[1] = *(const unsigned*)&sKh[n * FP + kk + 8];
                bl[0] = *(const unsigned*)&sKl[n * FP + kk    ];
                bl[1] = *(const unsigned*)&sKl[n * FP + kk + 8];
                mma16816(sc[nf], qh, bh);
                mma16816(sc[nf], qh, bl);
                mma16816(sc[nf], ql, bh);
            }
        }

        // ---- scale, causal mask, row stats ----
        const bool diag = (kb == qb);
        float rm0 = -1e30f, rm1 = -1e30f;
        #pragma unroll
        for (int nf = 0; nf < 8; nf++) {
            #pragma unroll
            for (int e = 0; e < 2; e++) {
                int kg = kb * 64 + nf * 8 + tg * 2 + e;
                float v0 = sc[nf][e] * scale;
                if (diag && kg > qrow0) v0 = -1e30f;
                sc[nf][e] = v0;
                rm0 = fmaxf(rm0, v0);
                float v1 = sc[nf][e + 2] * scale;
                if (diag && kg > qrow0 + 8) v1 = -1e30f;
                sc[nf][e + 2] = v1;
                rm1 = fmaxf(rm1, v1);
            }
        }
        rm0 = fmaxf(rm0, __shfl_xor_sync(0xffffffffu, rm0, 1));
        rm0 = fmaxf(rm0, __shfl_xor_sync(0xffffffffu, rm0, 2));
        rm1 = fmaxf(rm1, __shfl_xor_sync(0xffffffffu, rm1, 1));
        rm1 = fmaxf(rm1, __shfl_xor_sync(0xffffffffu, rm1, 2));

        const float mn0 = fmaxf(m0, rm0);
        const float mn1 = fmaxf(m1, rm1);
        const float a0 = exp2f((m0 - mn0) * LOG2E);
        const float a1 = exp2f((m1 - mn1) * LOG2E);
        m0 = mn0; m1 = mn1;
        l0 *= a0;  l1 *= a1;
        #pragma unroll
        for (int nf = 0; nf < 8; nf++) {
            oacc[nf][0] *= a0; oacc[nf][1] *= a0;
            oacc[nf][2] *= a1; oacc[nf][3] *= a1;
        }

        // ---- P = exp(S - m), row sums ----
        float rs0 = 0.f, rs1 = 0.f;
        #pragma unroll
        for (int nf = 0; nf < 8; nf++) {
            float p0 = exp2f((sc[nf][0] - mn0) * LOG2E);
            float p1 = exp2f((sc[nf][1] - mn0) * LOG2E);
            float p2 = exp2f((sc[nf][2] - mn1) * LOG2E);
            float p3 = exp2f((sc[nf][3] - mn1) * LOG2E);
            sc[nf][0] = p0; sc[nf][1] = p1; sc[nf][2] = p2; sc[nf][3] = p3;
            rs0 += p0 + p1; rs1 += p2 + p3;
        }
        rs0 += __shfl_xor_sync(0xffffffffu, rs0, 1);
        rs0 += __shfl_xor_sync(0xffffffffu, rs0, 2);
        rs1 += __shfl_xor_sync(0xffffffffu, rs1, 1);
        rs1 += __shfl_xor_sync(0xffffffffu, rs1, 2);
        l0 += rs0; l1 += rs1;

        // ---- pack P into split A-fragments ----
        unsigned ph[8][2], pl[8][2];
        #pragma unroll
        for (int nf = 0; nf < 8; nf++) {
            ph[nf][0] = pack2hi(sc[nf][0], sc[nf][1]);
            ph[nf][1] = pack2hi(sc[nf][2], sc[nf][3]);
            pl[nf][0] = pack2lo(sc[nf][0], sc[nf][1]);
            pl[nf][1] = pack2lo(sc[nf][2], sc[nf][3]);
        }

        // ---- O += P V (split, 3 products) ----
        #pragma unroll
        for (int kc = 0; kc < 4; kc++) {
            unsigned ah[4] = { ph[2*kc][0], ph[2*kc][1], ph[2*kc+1][0], ph[2*kc+1][1] };
            unsigned al[4] = { pl[2*kc][0], pl[2*kc][1], pl[2*kc+1][0], pl[2*kc+1][1] };
            const int kk = kc * 16 + tg * 2;
            #pragma unroll
            for (int nf = 0; nf < 8; nf++) {
                int n = nf * 8 + g;
                unsigned vh[2], vl[2];
                vh[0] = *(const unsigned*)&sVh[n * FP + kk    ];
                vh[1] = *(const unsigned*)&sVh[n * FP + kk + 8];
                vl[0] = *(const unsigned*)&sVl[n * FP + kk    ];
                vl[1] = *(const unsigned*)&sVl[n * FP + kk + 8];
                mma16816(oacc[nf], ah, vh);
                mma16816(oacc[nf], ah, vl);
                mma16816(oacc[nf], al, vh);
            }
        }
    }

    // ---- normalize + store split bf16 for O-projection ----
    const float inv0 = 1.0f / l0;
    const float inv1 = 1.0f / l1;
    const size_t rowbase = (size_t)(b * S_ + qb * 64);
    const int r0 = warp * 16 + g;
    #pragma unroll
    for (int nf = 0; nf < 8; nf++) {
        int c = head * DH_ + nf * 8 + tg * 2;
        float x0 = oacc[nf][0] * inv0, x1 = oacc[nf][1] * inv0;
        float x2 = oacc[nf][2] * inv1, x3 = oacc[nf][3] * inv1;
        *(unsigned*)&Oh[(rowbase + r0    ) * QKDIM_ + c] = pack2hi(x0, x1);
        *(unsigned*)&Ol[(rowbase + r0    ) * QKDIM_ + c] = pack2lo(x0, x1);
        *(unsigned*)&Oh[(rowbase + r0 + 8) * QKDIM_ + c] = pack2hi(x2, x3);
        *(unsigned*)&Ol[(rowbase + r0 + 8) * QKDIM_ + c] = pack2lo(x2, x3);
    }
}

// ---------------------------------------------------------------------------
extern "C" void kernel_launch(void* const* d_in, const int* in_sizes, int n_in,
                              void* d_out, int out_size)
{
    const float* X  = (const float*)d_in[0];
    const float* WQ = (const float*)d_in[1];
    const float* WK = (const float*)d_in[2];
    const float* WV = (const float*)d_in[3];
    const float* WO = (const float*)d_in[4];
    float* out = (float*)d_out;

    bf16 *xh, *xl, *wqh, *wql, *wkh, *wkl, *wvh, *wvl, *woh, *wol;
    bf16 *qh, *ql, *kh, *kl, *vh, *vl, *aoh, *aol;
    cudaGetSymbolAddress((void**)&xh,  sXh);  cudaGetSymbolAddress((void**)&xl,  sXl);
    cudaGetSymbolAddress((void**)&wqh, sWQh); cudaGetSymbolAddress((void**)&wql, sWQl);
    cudaGetSymbolAddress((void**)&wkh, sWKh); cudaGetSymbolAddress((void**)&wkl, sWKl);
    cudaGetSymbolAddress((void**)&wvh, sWVh); cudaGetSymbolAddress((void**)&wvl, sWVl);
    cudaGetSymbolAddress((void**)&woh, sWOh); cudaGetSymbolAddress((void**)&wol, sWOl);
    cudaGetSymbolAddress((void**)&qh,  sqh);  cudaGetSymbolAddress((void**)&ql,  sql);
    cudaGetSymbolAddress((void**)&kh,  skh);  cudaGetSymbolAddress((void**)&kl,  skl);
    cudaGetSymbolAddress((void**)&vh,  svh);  cudaGetSymbolAddress((void**)&vl,  svl);
    cudaGetSymbolAddress((void**)&aoh, saoh); cudaGetSymbolAddress((void**)&aol, saol);

    // ---- conversions ----
    {
        int n4;
        n4 = BS_ * DM_ / 4;
        k_split<<<(n4 + 255) / 256, 256>>>((const float4*)X,  (uint2*)xh,  (uint2*)xl,  n4);
        n4 = QKDIM_ * DM_ / 4;
        k_split<<<(n4 + 255) / 256, 256>>>((const float4*)WQ, (uint2*)wqh, (uint2*)wql, n4);
        n4 = KVDIM_ * DM_ / 4;
        k_split<<<(n4 + 255) / 256, 256>>>((const float4*)WK, (uint2*)wkh, (uint2*)wkl, n4);
        k_split<<<(n4 + 255) / 256, 256>>>((const float4*)WV, (uint2*)wvh, (uint2*)wvl, n4);
        k_split_t<<<dim3(DM_ / 32, QKDIM_ / 32), dim3(32, 8)>>>(WO, woh, wol);
    }

    const int GEMM_SMEM = 2 * 4 * GSTAGE * 2;   // 81920 bytes
    cudaFuncSetAttribute(gemm_nt<1>, cudaFuncAttributeMaxDynamicSharedMemorySize, GEMM_SMEM);
    cudaFuncSetAttribute(gemm_nt<0>, cudaFuncAttributeMaxDynamicSharedMemorySize, GEMM_SMEM);
    cudaFuncSetAttribute(flash_mma,  cudaFuncAttributeMaxDynamicSharedMemorySize, FA_SMEM);

    // ---- QKV projections (NT, split in / split out) ----
    gemm_nt<1><<<dim3(QKDIM_ / 128, BS_ / 128), 256, GEMM_SMEM>>>(
        xh, xl, wqh, wql, nullptr, qh, ql, BS_, QKDIM_, DM_);
    gemm_nt<1><<<dim3(KVDIM_ / 128, BS_ / 128), 256, GEMM_SMEM>>>(
        xh, xl, wkh, wkl, nullptr, kh, kl, BS_, KVDIM_, DM_);
    gemm_nt<1><<<dim3(KVDIM_ / 128, BS_ / 128), 256, GEMM_SMEM>>>(
        xh, xl, wvh, wvl, nullptr, vh, vl, BS_, KVDIM_, DM_);

    // ---- flash attention (split in / split out) ----
    flash_mma<<<dim3(S_ / 64, NH_, B_), 128, FA_SMEM>>>(qh, ql, kh, kl, vh, vl, aoh, aol);

    // ---- output projection (NT with pre-transposed W_O, fp32 out) ----
    gemm_nt<0><<<dim3(DM_ / 128, BS_ / 128), 256, GEMM_SMEM>>>(
        aoh, aol, woh, wol, out, nullptr, nullptr, BS_, DM_, DM_);
}

// round 15
// speedup vs baseline: 1.4821x; 1.1478x over previous
#include <cuda_runtime.h>
#include <cuda_bf16.h>
#include <math.h>

// Problem constants
#define B_   2
#define S_   2048
#define DM_  2048
#define NH_  32
#define NKV_ 8
#define DH_  64
#define BS_  (B_ * S_)          // 4096 rows
#define QKDIM_ (NH_ * DH_)      // 2048
#define KVDIM_ (NKV_ * DH_)     // 512

typedef __nv_bfloat16 bf16;

// ---------------------------------------------------------------------------
// Scratch (device globals). Everything between kernels is split bf16 hi/lo.
// ---------------------------------------------------------------------------
__device__ bf16 sXh [BS_ * DM_],     sXl [BS_ * DM_];
__device__ bf16 sWQh[QKDIM_ * DM_],  sWQl[QKDIM_ * DM_];
__device__ bf16 sWKh[KVDIM_ * DM_],  sWKl[KVDIM_ * DM_];
__device__ bf16 sWVh[KVDIM_ * DM_],  sWVl[KVDIM_ * DM_];
__device__ bf16 sWOh[DM_ * QKDIM_],  sWOl[DM_ * QKDIM_];   // transposed [n][k]
__device__ bf16 sqh [BS_ * QKDIM_],  sql [BS_ * QKDIM_];
__device__ bf16 skh [BS_ * KVDIM_],  skl [BS_ * KVDIM_];
__device__ bf16 svh [BS_ * KVDIM_],  svl [BS_ * KVDIM_];
__device__ bf16 saoh[BS_ * QKDIM_],  saol[BS_ * QKDIM_];

// ---------------------------------------------------------------------------
// Split helpers
// ---------------------------------------------------------------------------
__device__ __forceinline__ unsigned pack2hi(float a, float b)
{
    unsigned lo = __bfloat16_as_ushort(__float2bfloat16(a));
    unsigned hi = __bfloat16_as_ushort(__float2bfloat16(b));
    return lo | (hi << 16);
}
__device__ __forceinline__ unsigned pack2lo(float a, float b)
{
    float ra = a - __bfloat162float(__float2bfloat16(a));
    float rb = b - __bfloat162float(__float2bfloat16(b));
    return pack2hi(ra, rb);
}

// mma.sync m16n8k16 row.col bf16 -> f32 accumulate (in-place)
__device__ __forceinline__ void mma16816(float c[4], const unsigned a[4], const unsigned b[2])
{
    asm volatile(
        "mma.sync.aligned.m16n8k16.row.col.f32.bf16.bf16.f32 "
        "{%0,%1,%2,%3}, {%4,%5,%6,%7}, {%8,%9}, {%0,%1,%2,%3};\n"
        : "+f"(c[0]), "+f"(c[1]), "+f"(c[2]), "+f"(c[3])
        : "r"(a[0]), "r"(a[1]), "r"(a[2]), "r"(a[3]), "r"(b[0]), "r"(b[1]));
}

// cp.async 16B
__device__ __forceinline__ void cpa16(void* s, const void* g)
{
    unsigned sa = (unsigned)__cvta_generic_to_shared(s);
    asm volatile("cp.async.cg.shared.global [%0], [%1], 16;\n" :: "r"(sa), "l"(g) : "memory");
}
#define CP_COMMIT() asm volatile("cp.async.commit_group;\n" ::: "memory")
#define CP_WAIT1()  asm volatile("cp.async.wait_group 1;\n" ::: "memory")
#define CP_WAIT0()  asm volatile("cp.async.wait_group 0;\n" ::: "memory")

// ---------------------------------------------------------------------------
// Conversion kernels
// ---------------------------------------------------------------------------
__global__ void k_split(const float4* __restrict__ in, uint2* __restrict__ h,
                        uint2* __restrict__ l, int n4)
{
    int i = blockIdx.x * blockDim.x + threadIdx.x;
    if (i < n4) {
        float4 v = in[i];
        uint2 hh, ll;
        hh.x = pack2hi(v.x, v.y); hh.y = pack2hi(v.z, v.w);
        ll.x = pack2lo(v.x, v.y); ll.y = pack2lo(v.z, v.w);
        h[i] = hh; l[i] = ll;
    }
}

// split + transpose: in [K=2048][N=2048] fp32 -> th/tl [N][K] bf16
__global__ void k_split_t(const float* __restrict__ in, bf16* __restrict__ th,
                          bf16* __restrict__ tl)
{
    __shared__ float t[32][33];
    const int tx = threadIdx.x, ty = threadIdx.y;
    const int kin0 = blockIdx.y * 32;
    const int nin0 = blockIdx.x * 32;
    for (int j = ty; j < 32; j += 8)
        t[j][tx] = in[(size_t)(kin0 + j) * DM_ + nin0 + tx];
    __syncthreads();
    for (int j = ty; j < 32; j += 8) {
        float v = t[tx][j];
        size_t o = (size_t)(nin0 + j) * DM_ + kin0 + tx;
        bf16 hv = __float2bfloat16(v);
        th[o] = hv;
        tl[o] = __float2bfloat16(v - __bfloat162float(hv));
    }
}

// ---------------------------------------------------------------------------
// NT GEMM, pre-split bf16, cp.async double-buffered.
// C[M,N] = A[M,K] * B[N,K]^T (hi+lo, 3-product split accumulate).
// Block 128x128x32, 4 warps (2m x 2n), warp tile 64x64. 2 CTAs/SM.
// WRITE_SPLIT=1: write Ch/Cl bf16; else fp32 C.
// ---------------------------------------------------------------------------
#define GP 40                         // smem pitch in bf16 (80B rows, 16B-aligned)
#define GSTAGE (128 * GP)             // elems per array per stage

template <int WRITE_SPLIT>
__global__ __launch_bounds__(128)
void gemm_nt(const bf16* __restrict__ Agh, const bf16* __restrict__ Agl,
             const bf16* __restrict__ Bgh, const bf16* __restrict__ Bgl,
             float* __restrict__ C, bf16* __restrict__ Ch, bf16* __restrict__ Cl,
             int M, int N, int K)
{
    extern __shared__ __align__(16) bf16 sm[];
    const int tid  = threadIdx.x;
    const int m0   = blockIdx.y * 128;
    const int n0   = blockIdx.x * 128;
    const int warp = tid >> 5;
    const int lane = tid & 31;
    const int wm   = (warp & 1) * 64;
    const int wn   = (warp >> 1) * 64;
    const int g    = lane >> 2;
    const int tg   = lane & 3;

    float acc[4][8][4];
    #pragma unroll
    for (int i = 0; i < 4; i++)
        #pragma unroll
        for (int j = 0; j < 8; j++)
            #pragma unroll
            for (int r = 0; r < 4; r++) acc[i][j][r] = 0.f;

    const int T = K / 32;

    auto load_stage = [&](int st, int k0) {
        bf16* sAh = sm + (st * 4 + 0) * GSTAGE;
        bf16* sAl = sm + (st * 4 + 1) * GSTAGE;
        bf16* sBh = sm + (st * 4 + 2) * GSTAGE;
        bf16* sBl = sm + (st * 4 + 3) * GSTAGE;
        #pragma unroll
        for (int l = 0; l < 4; l++) {
            int idx = tid + l * 128;          // 0..511
            int row = idx >> 2, ch = idx & 3;
            int so  = row * GP + ch * 8;
            size_t ga = (size_t)(m0 + row) * K + k0 + ch * 8;
            size_t gb = (size_t)(n0 + row) * K + k0 + ch * 8;
            cpa16(sAh + so, Agh + ga);
            cpa16(sAl + so, Agl + ga);
            cpa16(sBh + so, Bgh + gb);
            cpa16(sBl + so, Bgl + gb);
        }
    };

    load_stage(0, 0);
    CP_COMMIT();

    for (int it = 0; it < T; it++) {
        if (it + 1 < T) {
            load_stage((it + 1) & 1, (it + 1) * 32);
            CP_COMMIT();
            CP_WAIT1();
        } else {
            CP_WAIT0();
        }
        __syncthreads();

        const int st = it & 1;
        const bf16* sAh = sm + (st * 4 + 0) * GSTAGE;
        const bf16* sAl = sm + (st * 4 + 1) * GSTAGE;
        const bf16* sBh = sm + (st * 4 + 2) * GSTAGE;
        const bf16* sBl = sm + (st * 4 + 3) * GSTAGE;

        #pragma unroll
        for (int kc = 0; kc < 32; kc += 16) {
            unsigned ah[4][4], al[4][4];
            #pragma unroll
            for (int mf = 0; mf < 4; mf++) {
                int r = wm + mf * 16 + g;
                ah[mf][0] = *(const unsigned*)&sAh[(r    ) * GP + kc + tg * 2    ];
                ah[mf][1] = *(const unsigned*)&sAh[(r + 8) * GP + kc + tg * 2    ];
                ah[mf][2] = *(const unsigned*)&sAh[(r    ) * GP + kc + tg * 2 + 8];
                ah[mf][3] = *(const unsigned*)&sAh[(r + 8) * GP + kc + tg * 2 + 8];
                al[mf][0] = *(const unsigned*)&sAl[(r    ) * GP + kc + tg * 2    ];
                al[mf][1] = *(const unsigned*)&sAl[(r + 8) * GP + kc + tg * 2    ];
                al[mf][2] = *(const unsigned*)&sAl[(r    ) * GP + kc + tg * 2 + 8];
                al[mf][3] = *(const unsigned*)&sAl[(r + 8) * GP + kc + tg * 2 + 8];
            }
            #pragma unroll
            for (int nf = 0; nf < 8; nf++) {
                int r = wn + nf * 8 + g;
                unsigned bh[2], bl[2];
                bh[0] = *(const unsigned*)&sBh[r * GP + kc + tg * 2    ];
                bh[1] = *(const unsigned*)&sBh[r * GP + kc + tg * 2 + 8];
                bl[0] = *(const unsigned*)&sBl[r * GP + kc + tg * 2    ];
                bl[1] = *(const unsigned*)&sBl[r * GP + kc + tg * 2 + 8];
                #pragma unroll
                for (int mf = 0; mf < 4; mf++) {
                    mma16816(acc[mf][nf], ah[mf], bh);
                    mma16816(acc[mf][nf], ah[mf], bl);
                    mma16816(acc[mf][nf], al[mf], bh);
                }
            }
        }
        __syncthreads();
    }

    #pragma unroll
    for (int mf = 0; mf < 4; mf++)
        #pragma unroll
        for (int nf = 0; nf < 8; nf++) {
            int r = m0 + wm + mf * 16 + g;
            int c = n0 + wn + nf * 8 + tg * 2;
            if (WRITE_SPLIT) {
                *(unsigned*)&Ch[(size_t)r * N + c]       = pack2hi(acc[mf][nf][0], acc[mf][nf][1]);
                *(unsigned*)&Cl[(size_t)r * N + c]       = pack2lo(acc[mf][nf][0], acc[mf][nf][1]);
                *(unsigned*)&Ch[(size_t)(r + 8) * N + c] = pack2hi(acc[mf][nf][2], acc[mf][nf][3]);
                *(unsigned*)&Cl[(size_t)(r + 8) * N + c] = pack2lo(acc[mf][nf][2], acc[mf][nf][3]);
            } else {
                *(float2*)&C[(size_t)r * N + c]       = make_float2(acc[mf][nf][0], acc[mf][nf][1]);
                *(float2*)&C[(size_t)(r + 8) * N + c] = make_float2(acc[mf][nf][2], acc[mf][nf][3]);
            }
        }
}

// ---------------------------------------------------------------------------
// Flash attention, tensor cores, split-bf16 gmem I/O.
// One block = 64 queries x one (batch, head). 128 threads = 4 warps.
// V transpose via word-pair __byte_perm (4B LDS/STS, no scalar stores).
// ---------------------------------------------------------------------------
#define FP 72
#define FA_ARR (64 * FP)
#define FA_SMEM (6 * FA_ARR * 2)        // 55296 bytes

__global__ __launch_bounds__(128)
void flash_mma(const bf16* __restrict__ Qh, const bf16* __restrict__ Ql,
               const bf16* __restrict__ Kh, const bf16* __restrict__ Kl,
               const bf16* __restrict__ Vh, const bf16* __restrict__ Vl,
               bf16* __restrict__ Oh, bf16* __restrict__ Ol)
{
    extern __shared__ __align__(16) bf16 smem[];
    bf16* sQh = smem;
    bf16* sQl = smem + 1 * FA_ARR;
    bf16* sKh = smem + 2 * FA_ARR;
    bf16* sKl = smem + 3 * FA_ARR;
    bf16* sVh = smem + 4 * FA_ARR;      // transposed: [d][key]
    bf16* sVl = smem + 5 * FA_ARR;

    const int qb   = blockIdx.x;
    const int head = blockIdx.y;
    const int b    = blockIdx.z;
    const int kvh  = head >> 2;
    const int tid  = threadIdx.x;
    const int warp = tid >> 5;
    const int lane = tid & 31;
    const int g    = lane >> 2;
    const int tg   = lane & 3;

    // ---- load Q tile (64x64 bf16 pairs), plain vector copies ----
    {
        const bf16* qhb = Qh + (size_t)(b * S_ + qb * 64) * QKDIM_ + head * DH_;
        const bf16* qlb = Ql + (size_t)(b * S_ + qb * 64) * QKDIM_ + head * DH_;
        for (int idx = tid; idx < 512; idx += 128) {
            int r = idx >> 3, ch = (idx & 7) * 8;
            *(uint4*)&sQh[r * FP + ch] = *(const uint4*)(qhb + (size_t)r * QKDIM_ + ch);
            *(uint4*)&sQl[r * FP + ch] = *(const uint4*)(qlb + (size_t)r * QKDIM_ + ch);
        }
    }

    float m0 = -INFINITY, m1 = -INFINITY, l0 = 0.f, l1 = 0.f;
    float oacc[8][4];
    #pragma unroll
    for (int nf = 0; nf < 8; nf++)
        #pragma unroll
        for (int e = 0; e < 4; e++) oacc[nf][e] = 0.f;

    const float scale = 0.125f;
    const float LOG2E = 1.44269504f;
    const int qrow0 = qb * 64 + warp * 16 + g;
    const int nkb = qb + 1;

    for (int kb = 0; kb < nkb; kb++) {
        __syncthreads();
        const bf16* khb = Kh + (size_t)(b * S_ + kb * 64) * KVDIM_ + kvh * DH_;
        const bf16* klb = Kl + (size_t)(b * S_ + kb * 64) * KVDIM_ + kvh * DH_;
        for (int idx = tid; idx < 512; idx += 128) {
            int r = idx >> 3, ch = (idx & 7) * 8;
            *(uint4*)&sKh[r * FP + ch] = *(const uint4*)(khb + (size_t)r * KVDIM_ + ch);
            *(uint4*)&sKl[r * FP + ch] = *(const uint4*)(klb + (size_t)r * KVDIM_ + ch);
        }
        // V transposed into smem [d][key] via word-pair byte_perm transposes
        const bf16* vhb = Vh + (size_t)(b * S_ + kb * 64) * KVDIM_ + kvh * DH_;
        const bf16* vlb = Vl + (size_t)(b * S_ + kb * 64) * KVDIM_ + kvh * DH_;
        for (int idx = tid; idx < 1024; idx += 128) {      // 32 keypairs x 32 d-words
            int kp = idx >> 5;          // 0..31 (keys 2kp, 2kp+1)
            int w  = idx & 31;          // 0..31 (ds 2w, 2w+1)
            unsigned a0 = *(const unsigned*)(vhb + (size_t)(2 * kp)     * KVDIM_ + 2 * w);
            unsigned a1 = *(const unsigned*)(vhb + (size_t)(2 * kp + 1) * KVDIM_ + 2 * w);
            *(unsigned*)&sVh[(2 * w    ) * FP + 2 * kp] = __byte_perm(a0, a1, 0x5410);
            *(unsigned*)&sVh[(2 * w + 1) * FP + 2 * kp] = __byte_perm(a0, a1, 0x7632);
            unsigned b0 = *(const unsigned*)(vlb + (size_t)(2 * kp)     * KVDIM_ + 2 * w);
            unsigned b1 = *(const unsigned*)(vlb + (size_t)(2 * kp + 1) * KVDIM_ + 2 * w);
            *(unsigned*)&sVl[(2 * w    ) * FP + 2 * kp] = __byte_perm(b0, b1, 0x5410);
            *(unsigned*)&sVl[(2 * w + 1) * FP + 2 * kp] = __byte_perm(b0, b1, 0x7632);
        }
        __syncthreads();

        // ---- S = Q K^T (split, 3 products) ----
        float sc[8][4];
        #pragma unroll
        for (int nf = 0; nf < 8; nf++)
            #pragma unroll
            for (int e = 0; e < 4; e++) sc[nf][e] = 0.f;

        #pragma unroll
        for (int kc = 0; kc < 4; kc++) {
            const int r0 = warp * 16 + g;
            const int kk = kc * 16 + tg * 2;
            unsigned qh[4], ql[4];
            qh[0] = *(const unsigned*)&sQh[(r0    ) * FP + kk    ];
            qh[1] = *(const unsigned*)&sQh[(r0 + 8) * FP + kk    ];
            qh[2] = *(const unsigned*)&sQh[(r0    ) * FP + kk + 8];
            qh[3] = *(const unsigned*)&sQh[(r0 + 8) * FP + kk + 8];
            ql[0] = *(const unsigned*)&sQl[(r0    ) * FP + kk    ];
            ql[1] = *(const unsigned*)&sQl[(r0 + 8) * FP + kk    ];
            ql[2] = *(const unsigned*)&sQl[(r0    ) * FP + kk + 8];
            ql[3] = *(const unsigned*)&sQl[(r0 + 8) * FP + kk + 8];
            #pragma unroll
            for (int nf = 0; nf < 8; nf++) {
                int n = nf * 8 + g;
                unsigned bh[2], bl[2];
                bh[0] = *(const unsigned*)&sKh[n * FP + kk    ];
                bh[1] = *(const unsigned*)&sKh[n * FP + kk + 8];
                bl[0] = *(const unsigned*)&sKl[n * FP + kk    ];
                bl[1] = *(const unsigned*)&sKl[n * FP + kk + 8];
                mma16816(sc[nf], qh, bh);
                mma16816(sc[nf], qh, bl);
                mma16816(sc[nf], ql, bh);
            }
        }

        // ---- scale, causal mask, row stats ----
        const bool diag = (kb == qb);
        float rm0 = -1e30f, rm1 = -1e30f;
        #pragma unroll
        for (int nf = 0; nf < 8; nf++) {
            #pragma unroll
            for (int e = 0; e < 2; e++) {
                int kg = kb * 64 + nf * 8 + tg * 2 + e;
                float v0 = sc[nf][e] * scale;
                if (diag && kg > qrow0) v0 = -1e30f;
                sc[nf][e] = v0;
                rm0 = fmaxf(rm0, v0);
                float v1 = sc[nf][e + 2] * scale;
                if (diag && kg > qrow0 + 8) v1 = -1e30f;
                sc[nf][e + 2] = v1;
                rm1 = fmaxf(rm1, v1);
            }
        }
        rm0 = fmaxf(rm0, __shfl_xor_sync(0xffffffffu, rm0, 1));
        rm0 = fmaxf(rm0, __shfl_xor_sync(0xffffffffu, rm0, 2));
        rm1 = fmaxf(rm1, __shfl_xor_sync(0xffffffffu, rm1, 1));
        rm1 = fmaxf(rm1, __shfl_xor_sync(0xffffffffu, rm1, 2));

        const float mn0 = fmaxf(m0, rm0);
        const float mn1 = fmaxf(m1, rm1);
        const float a0 = exp2f((m0 - mn0) * LOG2E);
        const float a1 = exp2f((m1 - mn1) * LOG2E);
        m0 = mn0; m1 = mn1;
        l0 *= a0;  l1 *= a1;
        #pragma unroll
        for (int nf = 0; nf < 8; nf++) {
            oacc[nf][0] *= a0; oacc[nf][1] *= a0;
            oacc[nf][2] *= a1; oacc[nf][3] *= a1;
        }

        // ---- P = exp(S - m), row sums ----
        float rs0 = 0.f, rs1 = 0.f;
        #pragma unroll
        for (int nf = 0; nf < 8; nf++) {
            float p0 = exp2f((sc[nf][0] - mn0) * LOG2E);
            float p1 = exp2f((sc[nf][1] - mn0) * LOG2E);
            float p2 = exp2f((sc[nf][2] - mn1) * LOG2E);
            float p3 = exp2f((sc[nf][3] - mn1) * LOG2E);
            sc[nf][0] = p0; sc[nf][1] = p1; sc[nf][2] = p2; sc[nf][3] = p3;
            rs0 += p0 + p1; rs1 += p2 + p3;
        }
        rs0 += __shfl_xor_sync(0xffffffffu, rs0, 1);
        rs0 += __shfl_xor_sync(0xffffffffu, rs0, 2);
        rs1 += __shfl_xor_sync(0xffffffffu, rs1, 1);
        rs1 += __shfl_xor_sync(0xffffffffu, rs1, 2);
        l0 += rs0; l1 += rs1;

        // ---- pack P into split A-fragments ----
        unsigned ph[8][2], pl[8][2];
        #pragma unroll
        for (int nf = 0; nf < 8; nf++) {
            ph[nf][0] = pack2hi(sc[nf][0], sc[nf][1]);
            ph[nf][1] = pack2hi(sc[nf][2], sc[nf][3]);
            pl[nf][0] = pack2lo(sc[nf][0], sc[nf][1]);
            pl[nf][1] = pack2lo(sc[nf][2], sc[nf][3]);
        }

        // ---- O += P V (split, 3 products) ----
        #pragma unroll
        for (int kc = 0; kc < 4; kc++) {
            unsigned ah[4] = { ph[2*kc][0], ph[2*kc][1], ph[2*kc+1][0], ph[2*kc+1][1] };
            unsigned al[4] = { pl[2*kc][0], pl[2*kc][1], pl[2*kc+1][0], pl[2*kc+1][1] };
            const int kk = kc * 16 + tg * 2;
            #pragma unroll
            for (int nf = 0; nf < 8; nf++) {
                int n = nf * 8 + g;
                unsigned vh[2], vl[2];
                vh[0] = *(const unsigned*)&sVh[n * FP + kk    ];
                vh[1] = *(const unsigned*)&sVh[n * FP + kk + 8];
                vl[0] = *(const unsigned*)&sVl[n * FP + kk    ];
                vl[1] = *(const unsigned*)&sVl[n * FP + kk + 8];
                mma16816(oacc[nf], ah, vh);
                mma16816(oacc[nf], ah, vl);
                mma16816(oacc[nf], al, vh);
            }
        }
    }

    // ---- normalize + store split bf16 for O-projection ----
    const float inv0 = 1.0f / l0;
    const float inv1 = 1.0f / l1;
    const size_t rowbase = (size_t)(b * S_ + qb * 64);
    const int r0 = warp * 16 + g;
    #pragma unroll
    for (int nf = 0; nf < 8; nf++) {
        int c = head * DH_ + nf * 8 + tg * 2;
        float x0 = oacc[nf][0] * inv0, x1 = oacc[nf][1] * inv0;
        float x2 = oacc[nf][2] * inv1, x3 = oacc[nf][3] * inv1;
        *(unsigned*)&Oh[(rowbase + r0    ) * QKDIM_ + c] = pack2hi(x0, x1);
        *(unsigned*)&Ol[(rowbase + r0    ) * QKDIM_ + c] = pack2lo(x0, x1);
        *(unsigned*)&Oh[(rowbase + r0 + 8) * QKDIM_ + c] = pack2hi(x2, x3);
        *(unsigned*)&Ol[(rowbase + r0 + 8) * QKDIM_ + c] = pack2lo(x2, x3);
    }
}

// ---------------------------------------------------------------------------
extern "C" void kernel_launch(void* const* d_in, const int* in_sizes, int n_in,
                              void* d_out, int out_size)
{
    const float* X  = (const float*)d_in[0];
    const float* WQ = (const float*)d_in[1];
    const float* WK = (const float*)d_in[2];
    const float* WV = (const float*)d_in[3];
    const float* WO = (const float*)d_in[4];
    float* out = (float*)d_out;

    bf16 *xh, *xl, *wqh, *wql, *wkh, *wkl, *wvh, *wvl, *woh, *wol;
    bf16 *qh, *ql, *kh, *kl, *vh, *vl, *aoh, *aol;
    cudaGetSymbolAddress((void**)&xh,  sXh);  cudaGetSymbolAddress((void**)&xl,  sXl);
    cudaGetSymbolAddress((void**)&wqh, sWQh); cudaGetSymbolAddress((void**)&wql, sWQl);
    cudaGetSymbolAddress((void**)&wkh, sWKh); cudaGetSymbolAddress((void**)&wkl, sWKl);
    cudaGetSymbolAddress((void**)&wvh, sWVh); cudaGetSymbolAddress((void**)&wvl, sWVl);
    cudaGetSymbolAddress((void**)&woh, sWOh); cudaGetSymbolAddress((void**)&wol, sWOl);
    cudaGetSymbolAddress((void**)&qh,  sqh);  cudaGetSymbolAddress((void**)&ql,  sql);
    cudaGetSymbolAddress((void**)&kh,  skh);  cudaGetSymbolAddress((void**)&kl,  skl);
    cudaGetSymbolAddress((void**)&vh,  svh);  cudaGetSymbolAddress((void**)&vl,  svl);
    cudaGetSymbolAddress((void**)&aoh, saoh); cudaGetSymbolAddress((void**)&aol, saol);

    // ---- conversions ----
    {
        int n4;
        n4 = BS_ * DM_ / 4;
        k_split<<<(n4 + 255) / 256, 256>>>((const float4*)X,  (uint2*)xh,  (uint2*)xl,  n4);
        n4 = QKDIM_ * DM_ / 4;
        k_split<<<(n4 + 255) / 256, 256>>>((const float4*)WQ, (uint2*)wqh, (uint2*)wql, n4);
        n4 = KVDIM_ * DM_ / 4;
        k_split<<<(n4 + 255) / 256, 256>>>((const float4*)WK, (uint2*)wkh, (uint2*)wkl, n4);
        k_split<<<(n4 + 255) / 256, 256>>>((const float4*)WV, (uint2*)wvh, (uint2*)wvl, n4);
        k_split_t<<<dim3(DM_ / 32, QKDIM_ / 32), dim3(32, 8)>>>(WO, woh, wol);
    }

    const int GEMM_SMEM = 2 * 4 * GSTAGE * 2;   // 81920 bytes
    cudaFuncSetAttribute(gemm_nt<1>, cudaFuncAttributeMaxDynamicSharedMemorySize, GEMM_SMEM);
    cudaFuncSetAttribute(gemm_nt<0>, cudaFuncAttributeMaxDynamicSharedMemorySize, GEMM_SMEM);
    cudaFuncSetAttribute(flash_mma,  cudaFuncAttributeMaxDynamicSharedMemorySize, FA_SMEM);

    // ---- QKV projections (NT, split in / split out) ----
    gemm_nt<1><<<dim3(QKDIM_ / 128, BS_ / 128), 128, GEMM_SMEM>>>(
        xh, xl, wqh, wql, nullptr, qh, ql, BS_, QKDIM_, DM_);
    gemm_nt<1><<<dim3(KVDIM_ / 128, BS_ / 128), 128, GEMM_SMEM>>>(
        xh, xl, wkh, wkl, nullptr, kh, kl, BS_, KVDIM_, DM_);
    gemm_nt<1><<<dim3(KVDIM_ / 128, BS_ / 128), 128, GEMM_SMEM>>>(
        xh, xl, wvh, wvl, nullptr, vh, vl, BS_, KVDIM_, DM_);

    // ---- flash attention (split in / split out) ----
    flash_mma<<<dim3(S_ / 64, NH_, B_), 128, FA_SMEM>>>(qh, ql, kh, kl, vh, vl, aoh, aol);

    // ---- output projection (NT with pre-transposed W_O, fp32 out) ----
    gemm_nt<0><<<dim3(DM_ / 128, BS_ / 128), 128, GEMM_SMEM>>>(
        aoh, aol, woh, wol, out, nullptr, nullptr, BS_, DM_, DM_);
}

// round 16
// speedup vs baseline: 1.5233x; 1.0278x over previous
#include <cuda_runtime.h>
#include <cuda_bf16.h>
#include <math.h>

// Problem constants
#define B_   2
#define S_   2048
#define DM_  2048
#define NH_  32
#define NKV_ 8
#define DH_  64
#define BS_  (B_ * S_)          // 4096 rows
#define QKDIM_ (NH_ * DH_)      // 2048
#define KVDIM_ (NKV_ * DH_)     // 512

typedef __nv_bfloat16 bf16;

// ---------------------------------------------------------------------------
// Scratch (device globals). Everything between kernels is split bf16 hi/lo.
// ---------------------------------------------------------------------------
__device__ bf16 sXh [BS_ * DM_],     sXl [BS_ * DM_];
__device__ bf16 sWQh[QKDIM_ * DM_],  sWQl[QKDIM_ * DM_];
__device__ bf16 sWKh[KVDIM_ * DM_],  sWKl[KVDIM_ * DM_];
__device__ bf16 sWVh[KVDIM_ * DM_],  sWVl[KVDIM_ * DM_];
__device__ bf16 sWOh[DM_ * QKDIM_],  sWOl[DM_ * QKDIM_];   // transposed [n][k]
__device__ bf16 sqh [BS_ * QKDIM_],  sql [BS_ * QKDIM_];
__device__ bf16 skh [BS_ * KVDIM_],  skl [BS_ * KVDIM_];
__device__ bf16 svh [BS_ * KVDIM_],  svl [BS_ * KVDIM_];
__device__ bf16 saoh[BS_ * QKDIM_],  saol[BS_ * QKDIM_];

// ---------------------------------------------------------------------------
// Split helpers
// ---------------------------------------------------------------------------
__device__ __forceinline__ unsigned pack2hi(float a, float b)
{
    unsigned lo = __bfloat16_as_ushort(__float2bfloat16(a));
    unsigned hi = __bfloat16_as_ushort(__float2bfloat16(b));
    return lo | (hi << 16);
}
__device__ __forceinline__ unsigned pack2lo(float a, float b)
{
    float ra = a - __bfloat162float(__float2bfloat16(a));
    float rb = b - __bfloat162float(__float2bfloat16(b));
    return pack2hi(ra, rb);
}

// mma.sync m16n8k16 row.col bf16 -> f32 accumulate (in-place)
__device__ __forceinline__ void mma16816(float c[4], const unsigned a[4], const unsigned b[2])
{
    asm volatile(
        "mma.sync.aligned.m16n8k16.row.col.f32.bf16.bf16.f32 "
        "{%0,%1,%2,%3}, {%4,%5,%6,%7}, {%8,%9}, {%0,%1,%2,%3};\n"
        : "+f"(c[0]), "+f"(c[1]), "+f"(c[2]), "+f"(c[3])
        : "r"(a[0]), "r"(a[1]), "r"(a[2]), "r"(a[3]), "r"(b[0]), "r"(b[1]));
}

// ldmatrix x4 (b16): 4 8x8 fragments in one instruction
#define LDSM_X4(r0, r1, r2, r3, addr) \
    asm volatile("ldmatrix.sync.aligned.m8n8.x4.shared.b16 {%0,%1,%2,%3}, [%4];" \
                 : "=r"(r0), "=r"(r1), "=r"(r2), "=r"(r3) : "r"(addr))

// cp.async 16B
__device__ __forceinline__ void cpa16(void* s, const void* g)
{
    unsigned sa = (unsigned)__cvta_generic_to_shared(s);
    asm volatile("cp.async.cg.shared.global [%0], [%1], 16;\n" :: "r"(sa), "l"(g) : "memory");
}
#define CP_COMMIT() asm volatile("cp.async.commit_group;\n" ::: "memory")
#define CP_WAIT1()  asm volatile("cp.async.wait_group 1;\n" ::: "memory")
#define CP_WAIT0()  asm volatile("cp.async.wait_group 0;\n" ::: "memory")

// ---------------------------------------------------------------------------
// Conversion kernels
// ---------------------------------------------------------------------------
__global__ void k_split(const float4* __restrict__ in, uint2* __restrict__ h,
                        uint2* __restrict__ l, int n4)
{
    int i = blockIdx.x * blockDim.x + threadIdx.x;
    if (i < n4) {
        float4 v = in[i];
        uint2 hh, ll;
        hh.x = pack2hi(v.x, v.y); hh.y = pack2hi(v.z, v.w);
        ll.x = pack2lo(v.x, v.y); ll.y = pack2lo(v.z, v.w);
        h[i] = hh; l[i] = ll;
    }
}

// split + transpose: in [K=2048][N=2048] fp32 -> th/tl [N][K] bf16
__global__ void k_split_t(const float* __restrict__ in, bf16* __restrict__ th,
                          bf16* __restrict__ tl)
{
    __shared__ float t[32][33];
    const int tx = threadIdx.x, ty = threadIdx.y;
    const int kin0 = blockIdx.y * 32;
    const int nin0 = blockIdx.x * 32;
    for (int j = ty; j < 32; j += 8)
        t[j][tx] = in[(size_t)(kin0 + j) * DM_ + nin0 + tx];
    __syncthreads();
    for (int j = ty; j < 32; j += 8) {
        float v = t[tx][j];
        size_t o = (size_t)(nin0 + j) * DM_ + kin0 + tx;
        bf16 hv = __float2bfloat16(v);
        th[o] = hv;
        tl[o] = __float2bfloat16(v - __bfloat162float(hv));
    }
}

// ---------------------------------------------------------------------------
// NT GEMM, pre-split bf16, cp.async double-buffered, LDSM fragment loads.
// C[M,N] = A[M,K] * B[N,K]^T (hi+lo, 3-product split accumulate).
// Block 128x128x32, 4 warps (2m x 2n), warp tile 64x64. 2 CTAs/SM.
// ---------------------------------------------------------------------------
#define GP 40                         // smem pitch in bf16 (80B rows, 16B-aligned)
#define GSTAGE (128 * GP)             // elems per array per stage

template <int WRITE_SPLIT>
__global__ __launch_bounds__(128)
void gemm_nt(const bf16* __restrict__ Agh, const bf16* __restrict__ Agl,
             const bf16* __restrict__ Bgh, const bf16* __restrict__ Bgl,
             float* __restrict__ C, bf16* __restrict__ Ch, bf16* __restrict__ Cl,
             int M, int N, int K)
{
    extern __shared__ __align__(16) bf16 sm[];
    const int tid  = threadIdx.x;
    const int m0   = blockIdx.y * 128;
    const int n0   = blockIdx.x * 128;
    const int warp = tid >> 5;
    const int lane = tid & 31;
    const int wm   = (warp & 1) * 64;
    const int wn   = (warp >> 1) * 64;
    const int g    = lane >> 2;
    const int tg   = lane & 3;

    float acc[4][8][4];
    #pragma unroll
    for (int i = 0; i < 4; i++)
        #pragma unroll
        for (int j = 0; j < 8; j++)
            #pragma unroll
            for (int r = 0; r < 4; r++) acc[i][j][r] = 0.f;

    const int T = K / 32;
    const unsigned smem_u32 = (unsigned)__cvta_generic_to_shared(sm);

    // --- precompute per-lane LDSM element offsets (in bf16 elems, kc=0) ---
    // A x4: row = wm + mf*16 + (lane&15), col = (lane>>4)*8
    unsigned aoff[4];
    #pragma unroll
    for (int mf = 0; mf < 4; mf++)
        aoff[mf] = (unsigned)((wm + mf * 16 + (lane & 15)) * GP + (lane >> 4) * 8);
    // B x4 (two nf per LDSM): row = wn + (nfp*2 + (lane>>4))*8 + (lane&7),
    //                         col = ((lane>>3)&1)*8
    unsigned boff[4];
    #pragma unroll
    for (int nfp = 0; nfp < 4; nfp++)
        boff[nfp] = (unsigned)((wn + (nfp * 2 + (lane >> 4)) * 8 + (lane & 7)) * GP
                               + ((lane >> 3) & 1) * 8);

    auto load_stage = [&](int st, int k0) {
        bf16* sAh = sm + (st * 4 + 0) * GSTAGE;
        bf16* sAl = sm + (st * 4 + 1) * GSTAGE;
        bf16* sBh = sm + (st * 4 + 2) * GSTAGE;
        bf16* sBl = sm + (st * 4 + 3) * GSTAGE;
        #pragma unroll
        for (int l = 0; l < 4; l++) {
            int idx = tid + l * 128;          // 0..511
            int row = idx >> 2, ch = idx & 3;
            int so  = row * GP + ch * 8;
            size_t ga = (size_t)(m0 + row) * K + k0 + ch * 8;
            size_t gb = (size_t)(n0 + row) * K + k0 + ch * 8;
            cpa16(sAh + so, Agh + ga);
            cpa16(sAl + so, Agl + ga);
            cpa16(sBh + so, Bgh + gb);
            cpa16(sBl + so, Bgl + gb);
        }
    };

    load_stage(0, 0);
    CP_COMMIT();

    for (int it = 0; it < T; it++) {
        if (it + 1 < T) {
            load_stage((it + 1) & 1, (it + 1) * 32);
            CP_COMMIT();
            CP_WAIT1();
        } else {
            CP_WAIT0();
        }
        __syncthreads();

        const int st = it & 1;
        const unsigned baseAh = smem_u32 + (st * 4 + 0) * GSTAGE * 2;
        const unsigned baseAl = smem_u32 + (st * 4 + 1) * GSTAGE * 2;
        const unsigned baseBh = smem_u32 + (st * 4 + 2) * GSTAGE * 2;
        const unsigned baseBl = smem_u32 + (st * 4 + 3) * GSTAGE * 2;

        #pragma unroll
        for (int kc = 0; kc < 32; kc += 16) {
            const unsigned kb = (unsigned)(kc * 2);   // byte offset for kc
            unsigned ah[4][4], al[4][4], bh[8][2], bl[8][2];
            #pragma unroll
            for (int mf = 0; mf < 4; mf++) {
                LDSM_X4(ah[mf][0], ah[mf][1], ah[mf][2], ah[mf][3], baseAh + aoff[mf] * 2 + kb);
                LDSM_X4(al[mf][0], al[mf][1], al[mf][2], al[mf][3], baseAl + aoff[mf] * 2 + kb);
            }
            #pragma unroll
            for (int nfp = 0; nfp < 4; nfp++) {
                LDSM_X4(bh[2*nfp][0], bh[2*nfp][1], bh[2*nfp+1][0], bh[2*nfp+1][1],
                        baseBh + boff[nfp] * 2 + kb);
                LDSM_X4(bl[2*nfp][0], bl[2*nfp][1], bl[2*nfp+1][0], bl[2*nfp+1][1],
                        baseBl + boff[nfp] * 2 + kb);
            }
            #pragma unroll
            for (int nf = 0; nf < 8; nf++)
                #pragma unroll
                for (int mf = 0; mf < 4; mf++) {
                    mma16816(acc[mf][nf], ah[mf], bh[nf]);
                    mma16816(acc[mf][nf], ah[mf], bl[nf]);
                    mma16816(acc[mf][nf], al[mf], bh[nf]);
                }
        }
        __syncthreads();
    }

    #pragma unroll
    for (int mf = 0; mf < 4; mf++)
        #pragma unroll
        for (int nf = 0; nf < 8; nf++) {
            int r = m0 + wm + mf * 16 + g;
            int c = n0 + wn + nf * 8 + tg * 2;
            if (WRITE_SPLIT) {
                *(unsigned*)&Ch[(size_t)r * N + c]       = pack2hi(acc[mf][nf][0], acc[mf][nf][1]);
                *(unsigned*)&Cl[(size_t)r * N + c]       = pack2lo(acc[mf][nf][0], acc[mf][nf][1]);
                *(unsigned*)&Ch[(size_t)(r + 8) * N + c] = pack2hi(acc[mf][nf][2], acc[mf][nf][3]);
                *(unsigned*)&Cl[(size_t)(r + 8) * N + c] = pack2lo(acc[mf][nf][2], acc[mf][nf][3]);
            } else {
                *(float2*)&C[(size_t)r * N + c]       = make_float2(acc[mf][nf][0], acc[mf][nf][1]);
                *(float2*)&C[(size_t)(r + 8) * N + c] = make_float2(acc[mf][nf][2], acc[mf][nf][3]);
            }
        }
}

// ---------------------------------------------------------------------------
// Flash attention (byte-identical to round 15 — 1411us config)
// ---------------------------------------------------------------------------
#define FP 72
#define FA_ARR (64 * FP)
#define FA_SMEM (6 * FA_ARR * 2)        // 55296 bytes

__global__ __launch_bounds__(128)
void flash_mma(const bf16* __restrict__ Qh, const bf16* __restrict__ Ql,
               const bf16* __restrict__ Kh, const bf16* __restrict__ Kl,
               const bf16* __restrict__ Vh, const bf16* __restrict__ Vl,
               bf16* __restrict__ Oh, bf16* __restrict__ Ol)
{
    extern __shared__ __align__(16) bf16 smem[];
    bf16* sQh = smem;
    bf16* sQl = smem + 1 * FA_ARR;
    bf16* sKh = smem + 2 * FA_ARR;
    bf16* sKl = smem + 3 * FA_ARR;
    bf16* sVh = smem + 4 * FA_ARR;      // transposed: [d][key]
    bf16* sVl = smem + 5 * FA_ARR;

    const int qb   = blockIdx.x;
    const int head = blockIdx.y;
    const int b    = blockIdx.z;
    const int kvh  = head >> 2;
    const int tid  = threadIdx.x;
    const int warp = tid >> 5;
    const int lane = tid & 31;
    const int g    = lane >> 2;
    const int tg   = lane & 3;

    {
        const bf16* qhb = Qh + (size_t)(b * S_ + qb * 64) * QKDIM_ + head * DH_;
        const bf16* qlb = Ql + (size_t)(b * S_ + qb * 64) * QKDIM_ + head * DH_;
        for (int idx = tid; idx < 512; idx += 128) {
            int r = idx >> 3, ch = (idx & 7) * 8;
            *(uint4*)&sQh[r * FP + ch] = *(const uint4*)(qhb + (size_t)r * QKDIM_ + ch);
            *(uint4*)&sQl[r * FP + ch] = *(const uint4*)(qlb + (size_t)r * QKDIM_ + ch);
        }
    }

    float m0 = -INFINITY, m1 = -INFINITY, l0 = 0.f, l1 = 0.f;
    float oacc[8][4];
    #pragma unroll
    for (int nf = 0; nf < 8; nf++)
        #pragma unroll
        for (int e = 0; e < 4; e++) oacc[nf][e] = 0.f;

    const float scale = 0.125f;
    const float LOG2E = 1.44269504f;
    const int qrow0 = qb * 64 + warp * 16 + g;
    const int nkb = qb + 1;

    for (int kb = 0; kb < nkb; kb++) {
        __syncthreads();
        const bf16* khb = Kh + (size_t)(b * S_ + kb * 64) * KVDIM_ + kvh * DH_;
        const bf16* klb = Kl + (size_t)(b * S_ + kb * 64) * KVDIM_ + kvh * DH_;
        for (int idx = tid; idx < 512; idx += 128) {
            int r = idx >> 3, ch = (idx & 7) * 8;
            *(uint4*)&sKh[r * FP + ch] = *(const uint4*)(khb + (size_t)r * KVDIM_ + ch);
            *(uint4*)&sKl[r * FP + ch] = *(const uint4*)(klb + (size_t)r * KVDIM_ + ch);
        }
        const bf16* vhb = Vh + (size_t)(b * S_ + kb * 64) * KVDIM_ + kvh * DH_;
        const bf16* vlb = Vl + (size_t)(b * S_ + kb * 64) * KVDIM_ + kvh * DH_;
        for (int idx = tid; idx < 1024; idx += 128) {
            int kp = idx >> 5;
            int w  = idx & 31;
            unsigned a0 = *(const unsigned*)(vhb + (size_t)(2 * kp)     * KVDIM_ + 2 * w);
            unsigned a1 = *(const unsigned*)(vhb + (size_t)(2 * kp + 1) * KVDIM_ + 2 * w);
            *(unsigned*)&sVh[(2 * w    ) * FP + 2 * kp] = __byte_perm(a0, a1, 0x5410);
            *(unsigned*)&sVh[(2 * w + 1) * FP + 2 * kp] = __byte_perm(a0, a1, 0x7632);
            unsigned b0 = *(const unsigned*)(vlb + (size_t)(2 * kp)     * KVDIM_ + 2 * w);
            unsigned b1 = *(const unsigned*)(vlb + (size_t)(2 * kp + 1) * KVDIM_ + 2 * w);
            *(unsigned*)&sVl[(2 * w    ) * FP + 2 * kp] = __byte_perm(b0, b1, 0x5410);
            *(unsigned*)&sVl[(2 * w + 1) * FP + 2 * kp] = __byte_perm(b0, b1, 0x7632);
        }
        __syncthreads();

        float sc[8][4];
        #pragma unroll
        for (int nf = 0; nf < 8; nf++)
            #pragma unroll
            for (int e = 0; e < 4; e++) sc[nf][e] = 0.f;

        #pragma unroll
        for (int kc = 0; kc < 4; kc++) {
            const int r0 = warp * 16 + g;
            const int kk = kc * 16 + tg * 2;
            unsigned qh[4], ql[4];
            qh[0] = *(const unsigned*)&sQh[(r0    ) * FP + kk    ];
            qh[1] = *(const unsigned*)&sQh[(r0 + 8) * FP + kk    ];
            qh[2] = *(const unsigned*)&sQh[(r0    ) * FP + kk + 8];
            qh[3] = *(const unsigned*)&sQh[(r0 + 8) * FP + kk + 8];
            ql[0] = *(const unsigned*)&sQl[(r0    ) * FP + kk    ];
            ql[1] = *(const unsigned*)&sQl[(r0 + 8) * FP + kk    ];
            ql[2] = *(const unsigned*)&sQl[(r0    ) * FP + kk + 8];
            ql[3] = *(const unsigned*)&sQl[(r0 + 8) * FP + kk + 8];
            #pragma unroll
            for (int nf = 0; nf < 8; nf++) {
                int n = nf * 8 + g;
                unsigned bh[2], bl[2];
                bh[0] = *(const unsigned*)&sKh[n * FP + kk    ];
                bh[1] = *(const unsigned*)&sKh[n * FP + kk + 8];
                bl[0] = *(const unsigned*)&sKl[n * FP + kk    ];
                bl[1] = *(const unsigned*)&sKl[n * FP + kk + 8];
                mma16816(sc[nf], qh, bh);
                mma16816(sc[nf], qh, bl);
                mma16816(sc[nf], ql, bh);
            }
        }

        const bool diag = (kb == qb);
        float rm0 = -1e30f, rm1 = -1e30f;
        #pragma unroll
        for (int nf = 0; nf < 8; nf++) {
            #pragma unroll
            for (int e = 0; e < 2; e++) {
                int kg = kb * 64 + nf * 8 + tg * 2 + e;
                float v0 = sc[nf][e] * scale;
                if (diag && kg > qrow0) v0 = -1e30f;
                sc[nf][e] = v0;
                rm0 = fmaxf(rm0, v0);
                float v1 = sc[nf][e + 2] * scale;
                if (diag && kg > qrow0 + 8) v1 = -1e30f;
                sc[nf][e + 2] = v1;
                rm1 = fmaxf(rm1, v1);
            }
        }
        rm0 = fmaxf(rm0, __shfl_xor_sync(0xffffffffu, rm0, 1));
        rm0 = fmaxf(rm0, __shfl_xor_sync(0xffffffffu, rm0, 2));
        rm1 = fmaxf(rm1, __shfl_xor_sync(0xffffffffu, rm1, 1));
        rm1 = fmaxf(rm1, __shfl_xor_sync(0xffffffffu, rm1, 2));

        const float mn0 = fmaxf(m0, rm0);
        const float mn1 = fmaxf(m1, rm1);
        const float a0 = exp2f((m0 - mn0) * LOG2E);
        const float a1 = exp2f((m1 - mn1) * LOG2E);
        m0 = mn0; m1 = mn1;
        l0 *= a0;  l1 *= a1;
        #pragma unroll
        for (int nf = 0; nf < 8; nf++) {
            oacc[nf][0] *= a0; oacc[nf][1] *= a0;
            oacc[nf][2] *= a1; oacc[nf][3] *= a1;
        }

        float rs0 = 0.f, rs1 = 0.f;
        #pragma unroll
        for (int nf = 0; nf < 8; nf++) {
            float p0 = exp2f((sc[nf][0] - mn0) * LOG2E);
            float p1 = exp2f((sc[nf][1] - mn0) * LOG2E);
            float p2 = exp2f((sc[nf][2] - mn1) * LOG2E);
            float p3 = exp2f((sc[nf][3] - mn1) * LOG2E);
            sc[nf][0] = p0; sc[nf][1] = p1; sc[nf][2] = p2; sc[nf][3] = p3;
            rs0 += p0 + p1; rs1 += p2 + p3;
        }
        rs0 += __shfl_xor_sync(0xffffffffu, rs0, 1);
        rs0 += __shfl_xor_sync(0xffffffffu, rs0, 2);
        rs1 += __shfl_xor_sync(0xffffffffu, rs1, 1);
        rs1 += __shfl_xor_sync(0xffffffffu, rs1, 2);
        l0 += rs0; l1 += rs1;

        unsigned ph[8][2], pl[8][2];
        #pragma unroll
        for (int nf = 0; nf < 8; nf++) {
            ph[nf][0] = pack2hi(sc[nf][0], sc[nf][1]);
            ph[nf][1] = pack2hi(sc[nf][2], sc[nf][3]);
            pl[nf][0] = pack2lo(sc[nf][0], sc[nf][1]);
            pl[nf][1] = pack2lo(sc[nf][2], sc[nf][3]);
        }

        #pragma unroll
        for (int kc = 0; kc < 4; kc++) {
            unsigned ah[4] = { ph[2*kc][0], ph[2*kc][1], ph[2*kc+1][0], ph[2*kc+1][1] };
            unsigned al[4] = { pl[2*kc][0], pl[2*kc][1], pl[2*kc+1][0], pl[2*kc+1][1] };
            const int kk = kc * 16 + tg * 2;
            #pragma unroll
            for (int nf = 0; nf < 8; nf++) {
                int n = nf * 8 + g;
                unsigned vh[2], vl[2];
                vh[0] = *(const unsigned*)&sVh[n * FP + kk    ];
                vh[1] = *(const unsigned*)&sVh[n * FP + kk + 8];
                vl[0] = *(const unsigned*)&sVl[n * FP + kk    ];
                vl[1] = *(const unsigned*)&sVl[n * FP + kk + 8];
                mma16816(oacc[nf], ah, vh);
                mma16816(oacc[nf], ah, vl);
                mma16816(oacc[nf], al, vh);
            }
        }
    }

    const float inv0 = 1.0f / l0;
    const float inv1 = 1.0f / l1;
    const size_t rowbase = (size_t)(b * S_ + qb * 64);
    const int r0 = warp * 16 + g;
    #pragma unroll
    for (int nf = 0; nf < 8; nf++) {
        int c = head * DH_ + nf * 8 + tg * 2;
        float x0 = oacc[nf][0] * inv0, x1 = oacc[nf][1] * inv0;
        float x2 = oacc[nf][2] * inv1, x3 = oacc[nf][3] * inv1;
        *(unsigned*)&Oh[(rowbase + r0    ) * QKDIM_ + c] = pack2hi(x0, x1);
        *(unsigned*)&Ol[(rowbase + r0    ) * QKDIM_ + c] = pack2lo(x0, x1);
        *(unsigned*)&Oh[(rowbase + r0 + 8) * QKDIM_ + c] = pack2hi(x2, x3);
        *(unsigned*)&Ol[(rowbase + r0 + 8) * QKDIM_ + c] = pack2lo(x2, x3);
    }
}

// ---------------------------------------------------------------------------
extern "C" void kernel_launch(void* const* d_in, const int* in_sizes, int n_in,
                              void* d_out, int out_size)
{
    const float* X  = (const float*)d_in[0];
    const float* WQ = (const float*)d_in[1];
    const float* WK = (const float*)d_in[2];
    const float* WV = (const float*)d_in[3];
    const float* WO = (const float*)d_in[4];
    float* out = (float*)d_out;

    bf16 *xh, *xl, *wqh, *wql, *wkh, *wkl, *wvh, *wvl, *woh, *wol;
    bf16 *qh, *ql, *kh, *kl, *vh, *vl, *aoh, *aol;
    cudaGetSymbolAddress((void**)&xh,  sXh);  cudaGetSymbolAddress((void**)&xl,  sXl);
    cudaGetSymbolAddress((void**)&wqh, sWQh); cudaGetSymbolAddress((void**)&wql, sWQl);
    cudaGetSymbolAddress((void**)&wkh, sWKh); cudaGetSymbolAddress((void**)&wkl, sWKl);
    cudaGetSymbolAddress((void**)&wvh, sWVh); cudaGetSymbolAddress((void**)&wvl, sWVl);
    cudaGetSymbolAddress((void**)&woh, sWOh); cudaGetSymbolAddress((void**)&wol, sWOl);
    cudaGetSymbolAddress((void**)&qh,  sqh);  cudaGetSymbolAddress((void**)&ql,  sql);
    cudaGetSymbolAddress((void**)&kh,  skh);  cudaGetSymbolAddress((void**)&kl,  skl);
    cudaGetSymbolAddress((void**)&vh,  svh);  cudaGetSymbolAddress((void**)&vl,  svl);
    cudaGetSymbolAddress((void**)&aoh, saoh); cudaGetSymbolAddress((void**)&aol, saol);

    // ---- conversions ----
    {
        int n4;
        n4 = BS_ * DM_ / 4;
        k_split<<<(n4 + 255) / 256, 256>>>((const float4*)X,  (uint2*)xh,  (uint2*)xl,  n4);
        n4 = QKDIM_ * DM_ / 4;
        k_split<<<(n4 + 255) / 256, 256>>>((const float4*)WQ, (uint2*)wqh, (uint2*)wql, n4);
        n4 = KVDIM_ * DM_ / 4;
        k_split<<<(n4 + 255) / 256, 256>>>((const float4*)WK, (uint2*)wkh, (uint2*)wkl, n4);
        k_split<<<(n4 + 255) / 256, 256>>>((const float4*)WV, (uint2*)wvh, (uint2*)wvl, n4);
        k_split_t<<<dim3(DM_ / 32, QKDIM_ / 32), dim3(32, 8)>>>(WO, woh, wol);
    }

    const int GEMM_SMEM = 2 * 4 * GSTAGE * 2;   // 81920 bytes
    cudaFuncSetAttribute(gemm_nt<1>, cudaFuncAttributeMaxDynamicSharedMemorySize, GEMM_SMEM);
    cudaFuncSetAttribute(gemm_nt<0>, cudaFuncAttributeMaxDynamicSharedMemorySize, GEMM_SMEM);
    cudaFuncSetAttribute(flash_mma,  cudaFuncAttributeMaxDynamicSharedMemorySize, FA_SMEM);

    // ---- QKV projections (NT, split in / split out) ----
    gemm_nt<1><<<dim3(QKDIM_ / 128, BS_ / 128), 128, GEMM_SMEM>>>(
        xh, xl, wqh, wql, nullptr, qh, ql, BS_, QKDIM_, DM_);
    gemm_nt<1><<<dim3(KVDIM_ / 128, BS_ / 128), 128, GEMM_SMEM>>>(
        xh, xl, wkh, wkl, nullptr, kh, kl, BS_, KVDIM_, DM_);
    gemm_nt<1><<<dim3(KVDIM_ / 128, BS_ / 128), 128, GEMM_SMEM>>>(
        xh, xl, wvh, wvl, nullptr, vh, vl, BS_, KVDIM_, DM_);

    // ---- flash attention (split in / split out) ----
    flash_mma<<<dim3(S_ / 64, NH_, B_), 128, FA_SMEM>>>(qh, ql, kh, kl, vh, vl, aoh, aol);

    // ---- output projection (NT with pre-transposed W_O, fp32 out) ----
    gemm_nt<0><<<dim3(DM_ / 128, BS_ / 128), 128, GEMM_SMEM>>>(
        aoh, aol, woh, wol, out, nullptr, nullptr, BS_, DM_, DM_);
}

// round 17
// speedup vs baseline: 2.3634x; 1.5515x over previous
#include <cuda_runtime.h>
#include <cuda_bf16.h>
#include <cuda_fp16.h>
#include <math.h>

// Problem constants
#define B_   2
#define S_   2048
#define DM_  2048
#define NH_  32
#define NKV_ 8
#define DH_  64
#define BS_  (B_ * S_)          // 4096 rows
#define QKDIM_ (NH_ * DH_)      // 2048
#define KVDIM_ (NKV_ * DH_)     // 512

typedef __nv_bfloat16 bf16;

// ---------------------------------------------------------------------------
// Scratch (device globals).
// Projection inputs: single fp16. Flash inputs: split bf16. Flash out: fp16.
// ---------------------------------------------------------------------------
__device__ __half hX  [BS_ * DM_];
__device__ __half hWQ [QKDIM_ * DM_];
__device__ __half hWK [KVDIM_ * DM_];
__device__ __half hWV [KVDIM_ * DM_];
__device__ __half hWOt[DM_ * QKDIM_];      // transposed [n=dmodel][k=headcol]
__device__ __half hAO [BS_ * QKDIM_];
__device__ bf16 sqh [BS_ * QKDIM_],  sql [BS_ * QKDIM_];
__device__ bf16 skh [BS_ * KVDIM_],  skl [BS_ * KVDIM_];
__device__ bf16 svh [BS_ * KVDIM_],  svl [BS_ * KVDIM_];

// ---------------------------------------------------------------------------
// Helpers
// ---------------------------------------------------------------------------
__device__ __forceinline__ unsigned pack2hi(float a, float b)
{
    unsigned lo = __bfloat16_as_ushort(__float2bfloat16(a));
    unsigned hi = __bfloat16_as_ushort(__float2bfloat16(b));
    return lo | (hi << 16);
}
__device__ __forceinline__ unsigned pack2lo(float a, float b)
{
    float ra = a - __bfloat162float(__float2bfloat16(a));
    float rb = b - __bfloat162float(__float2bfloat16(b));
    return pack2hi(ra, rb);
}
__device__ __forceinline__ unsigned pack2half(float a, float b)
{
    unsigned lo = __half_as_ushort(__float2half_rn(a));
    unsigned hi = __half_as_ushort(__float2half_rn(b));
    return lo | (hi << 16);
}

// mma.sync m16n8k16 row.col bf16 -> f32 accumulate
__device__ __forceinline__ void mma16816(float c[4], const unsigned a[4], const unsigned b[2])
{
    asm volatile(
        "mma.sync.aligned.m16n8k16.row.col.f32.bf16.bf16.f32 "
        "{%0,%1,%2,%3}, {%4,%5,%6,%7}, {%8,%9}, {%0,%1,%2,%3};\n"
        : "+f"(c[0]), "+f"(c[1]), "+f"(c[2]), "+f"(c[3])
        : "r"(a[0]), "r"(a[1]), "r"(a[2]), "r"(a[3]), "r"(b[0]), "r"(b[1]));
}
// mma.sync m16n8k16 row.col fp16 -> f32 accumulate
__device__ __forceinline__ void mma16816h(float c[4], const unsigned a[4], const unsigned b[2])
{
    asm volatile(
        "mma.sync.aligned.m16n8k16.row.col.f32.f16.f16.f32 "
        "{%0,%1,%2,%3}, {%4,%5,%6,%7}, {%8,%9}, {%0,%1,%2,%3};\n"
        : "+f"(c[0]), "+f"(c[1]), "+f"(c[2]), "+f"(c[3])
        : "r"(a[0]), "r"(a[1]), "r"(a[2]), "r"(a[3]), "r"(b[0]), "r"(b[1]));
}

// ldmatrix x4 (b16)
#define LDSM_X4(r0, r1, r2, r3, addr) \
    asm volatile("ldmatrix.sync.aligned.m8n8.x4.shared.b16 {%0,%1,%2,%3}, [%4];" \
                 : "=r"(r0), "=r"(r1), "=r"(r2), "=r"(r3) : "r"(addr))

// cp.async 16B
__device__ __forceinline__ void cpa16(void* s, const void* g)
{
    unsigned sa = (unsigned)__cvta_generic_to_shared(s);
    asm volatile("cp.async.cg.shared.global [%0], [%1], 16;\n" :: "r"(sa), "l"(g) : "memory");
}
#define CP_COMMIT() asm volatile("cp.async.commit_group;\n" ::: "memory")
#define CP_WAIT1()  asm volatile("cp.async.wait_group 1;\n" ::: "memory")
#define CP_WAIT0()  asm volatile("cp.async.wait_group 0;\n" ::: "memory")

// ---------------------------------------------------------------------------
// Conversion kernels: fp32 -> fp16 (single), and transposed variant for WO.
// ---------------------------------------------------------------------------
__global__ void k_half(const float4* __restrict__ in, uint2* __restrict__ h, int n4)
{
    int i = blockIdx.x * blockDim.x + threadIdx.x;
    if (i < n4) {
        float4 v = in[i];
        uint2 o;
        o.x = pack2half(v.x, v.y);
        o.y = pack2half(v.z, v.w);
        h[i] = o;
    }
}

// in [K=2048][N=2048] fp32 -> out [N][K] fp16
__global__ void k_half_t(const float* __restrict__ in, __half* __restrict__ th)
{
    __shared__ float t[32][33];
    const int tx = threadIdx.x, ty = threadIdx.y;
    const int kin0 = blockIdx.y * 32;
    const int nin0 = blockIdx.x * 32;
    for (int j = ty; j < 32; j += 8)
        t[j][tx] = in[(size_t)(kin0 + j) * DM_ + nin0 + tx];
    __syncthreads();
    for (int j = ty; j < 32; j += 8) {
        float v = t[tx][j];
        th[(size_t)(nin0 + j) * DM_ + kin0 + tx] = __float2half_rn(v);
    }
}

// ---------------------------------------------------------------------------
// NT GEMM, single fp16 operands, cp.async double-buffered, LDSM loads.
// C[M,N] = A[M,K] * B[N,K]^T, fp32 accumulate.
// Block 128x128x32, 4 warps (2m x 2n), warp tile 64x64.
// WRITE_SPLIT=1: write bf16 hi/lo (flash inputs); else fp32 C.
// ---------------------------------------------------------------------------
#define GP 40                         // smem pitch in halfs (80B rows)
#define GSTAGE (128 * GP)             // elems per array per stage

template <int WRITE_SPLIT>
__global__ __launch_bounds__(128)
void gemm_nt(const __half* __restrict__ Ag, const __half* __restrict__ Bg,
             float* __restrict__ C, bf16* __restrict__ Ch, bf16* __restrict__ Cl,
             int M, int N, int K)
{
    extern __shared__ __align__(16) __half sm[];
    const int tid  = threadIdx.x;
    const int m0   = blockIdx.y * 128;
    const int n0   = blockIdx.x * 128;
    const int warp = tid >> 5;
    const int lane = tid & 31;
    const int wm   = (warp & 1) * 64;
    const int wn   = (warp >> 1) * 64;
    const int g    = lane >> 2;
    const int tg   = lane & 3;

    float acc[4][8][4];
    #pragma unroll
    for (int i = 0; i < 4; i++)
        #pragma unroll
        for (int j = 0; j < 8; j++)
            #pragma unroll
            for (int r = 0; r < 4; r++) acc[i][j][r] = 0.f;

    const int T = K / 32;
    const unsigned smem_u32 = (unsigned)__cvta_generic_to_shared(sm);

    // per-lane LDSM element offsets (halfs, kc=0)
    unsigned aoff[4];
    #pragma unroll
    for (int mf = 0; mf < 4; mf++)
        aoff[mf] = (unsigned)((wm + mf * 16 + (lane & 15)) * GP + (lane >> 4) * 8);
    unsigned boff[4];
    #pragma unroll
    for (int nfp = 0; nfp < 4; nfp++)
        boff[nfp] = (unsigned)((wn + (nfp * 2 + (lane >> 4)) * 8 + (lane & 7)) * GP
                               + ((lane >> 3) & 1) * 8);

    auto load_stage = [&](int st, int k0) {
        __half* sA = sm + (st * 2 + 0) * GSTAGE;
        __half* sB = sm + (st * 2 + 1) * GSTAGE;
        #pragma unroll
        for (int l = 0; l < 4; l++) {
            int idx = tid + l * 128;          // 0..511
            int row = idx >> 2, ch = idx & 3;
            int so  = row * GP + ch * 8;
            cpa16(sA + so, Ag + (size_t)(m0 + row) * K + k0 + ch * 8);
            cpa16(sB + so, Bg + (size_t)(n0 + row) * K + k0 + ch * 8);
        }
    };

    load_stage(0, 0);
    CP_COMMIT();

    for (int it = 0; it < T; it++) {
        if (it + 1 < T) {
            load_stage((it + 1) & 1, (it + 1) * 32);
            CP_COMMIT();
            CP_WAIT1();
        } else {
            CP_WAIT0();
        }
        __syncthreads();

        const int st = it & 1;
        const unsigned baseA = smem_u32 + (st * 2 + 0) * GSTAGE * 2;
        const unsigned baseB = smem_u32 + (st * 2 + 1) * GSTAGE * 2;

        #pragma unroll
        for (int kc = 0; kc < 32; kc += 16) {
            const unsigned kb = (unsigned)(kc * 2);
            unsigned a[4][4], b[8][2];
            #pragma unroll
            for (int mf = 0; mf < 4; mf++)
                LDSM_X4(a[mf][0], a[mf][1], a[mf][2], a[mf][3], baseA + aoff[mf] * 2 + kb);
            #pragma unroll
            for (int nfp = 0; nfp < 4; nfp++)
                LDSM_X4(b[2*nfp][0], b[2*nfp][1], b[2*nfp+1][0], b[2*nfp+1][1],
                        baseB + boff[nfp] * 2 + kb);
            #pragma unroll
            for (int nf = 0; nf < 8; nf++)
                #pragma unroll
                for (int mf = 0; mf < 4; mf++)
                    mma16816h(acc[mf][nf], a[mf], b[nf]);
        }
        __syncthreads();
    }

    #pragma unroll
    for (int mf = 0; mf < 4; mf++)
        #pragma unroll
        for (int nf = 0; nf < 8; nf++) {
            int r = m0 + wm + mf * 16 + g;
            int c = n0 + wn + nf * 8 + tg * 2;
            if (WRITE_SPLIT) {
                *(unsigned*)&Ch[(size_t)r * N + c]       = pack2hi(acc[mf][nf][0], acc[mf][nf][1]);
                *(unsigned*)&Cl[(size_t)r * N + c]       = pack2lo(acc[mf][nf][0], acc[mf][nf][1]);
                *(unsigned*)&Ch[(size_t)(r + 8) * N + c] = pack2hi(acc[mf][nf][2], acc[mf][nf][3]);
                *(unsigned*)&Cl[(size_t)(r + 8) * N + c] = pack2lo(acc[mf][nf][2], acc[mf][nf][3]);
            } else {
                *(float2*)&C[(size_t)r * N + c]       = make_float2(acc[mf][nf][0], acc[mf][nf][1]);
                *(float2*)&C[(size_t)(r + 8) * N + c] = make_float2(acc[mf][nf][2], acc[mf][nf][3]);
            }
        }
}

// ---------------------------------------------------------------------------
// Flash attention — internals byte-identical to round 16 (validated);
// epilogue now writes fp16 (for the fp16 O-projection).
// ---------------------------------------------------------------------------
#define FP 72
#define FA_ARR (64 * FP)
#define FA_SMEM (6 * FA_ARR * 2)        // 55296 bytes

__global__ __launch_bounds__(128)
void flash_mma(const bf16* __restrict__ Qh, const bf16* __restrict__ Ql,
               const bf16* __restrict__ Kh, const bf16* __restrict__ Kl,
               const bf16* __restrict__ Vh, const bf16* __restrict__ Vl,
               __half* __restrict__ AO)
{
    extern __shared__ __align__(16) bf16 smem[];
    bf16* sQh = smem;
    bf16* sQl = smem + 1 * FA_ARR;
    bf16* sKh = smem + 2 * FA_ARR;
    bf16* sKl = smem + 3 * FA_ARR;
    bf16* sVh = smem + 4 * FA_ARR;      // transposed: [d][key]
    bf16* sVl = smem + 5 * FA_ARR;

    const int qb   = blockIdx.x;
    const int head = blockIdx.y;
    const int b    = blockIdx.z;
    const int kvh  = head >> 2;
    const int tid  = threadIdx.x;
    const int warp = tid >> 5;
    const int lane = tid & 31;
    const int g    = lane >> 2;
    const int tg   = lane & 3;

    {
        const bf16* qhb = Qh + (size_t)(b * S_ + qb * 64) * QKDIM_ + head * DH_;
        const bf16* qlb = Ql + (size_t)(b * S_ + qb * 64) * QKDIM_ + head * DH_;
        for (int idx = tid; idx < 512; idx += 128) {
            int r = idx >> 3, ch = (idx & 7) * 8;
            *(uint4*)&sQh[r * FP + ch] = *(const uint4*)(qhb + (size_t)r * QKDIM_ + ch);
            *(uint4*)&sQl[r * FP + ch] = *(const uint4*)(qlb + (size_t)r * QKDIM_ + ch);
        }
    }

    float m0 = -INFINITY, m1 = -INFINITY, l0 = 0.f, l1 = 0.f;
    float oacc[8][4];
    #pragma unroll
    for (int nf = 0; nf < 8; nf++)
        #pragma unroll
        for (int e = 0; e < 4; e++) oacc[nf][e] = 0.f;

    const float scale = 0.125f;
    const float LOG2E = 1.44269504f;
    const int qrow0 = qb * 64 + warp * 16 + g;
    const int nkb = qb + 1;

    for (int kb = 0; kb < nkb; kb++) {
        __syncthreads();
        const bf16* khb = Kh + (size_t)(b * S_ + kb * 64) * KVDIM_ + kvh * DH_;
        const bf16* klb = Kl + (size_t)(b * S_ + kb * 64) * KVDIM_ + kvh * DH_;
        for (int idx = tid; idx < 512; idx += 128) {
            int r = idx >> 3, ch = (idx & 7) * 8;
            *(uint4*)&sKh[r * FP + ch] = *(const uint4*)(khb + (size_t)r * KVDIM_ + ch);
            *(uint4*)&sKl[r * FP + ch] = *(const uint4*)(klb + (size_t)r * KVDIM_ + ch);
        }
        const bf16* vhb = Vh + (size_t)(b * S_ + kb * 64) * KVDIM_ + kvh * DH_;
        const bf16* vlb = Vl + (size_t)(b * S_ + kb * 64) * KVDIM_ + kvh * DH_;
        for (int idx = tid; idx < 1024; idx += 128) {
            int kp = idx >> 5;
            int w  = idx & 31;
            unsigned a0 = *(const unsigned*)(vhb + (size_t)(2 * kp)     * KVDIM_ + 2 * w);
            unsigned a1 = *(const unsigned*)(vhb + (size_t)(2 * kp + 1) * KVDIM_ + 2 * w);
            *(unsigned*)&sVh[(2 * w    ) * FP + 2 * kp] = __byte_perm(a0, a1, 0x5410);
            *(unsigned*)&sVh[(2 * w + 1) * FP + 2 * kp] = __byte_perm(a0, a1, 0x7632);
            unsigned b0 = *(const unsigned*)(vlb + (size_t)(2 * kp)     * KVDIM_ + 2 * w);
            unsigned b1 = *(const unsigned*)(vlb + (size_t)(2 * kp + 1) * KVDIM_ + 2 * w);
            *(unsigned*)&sVl[(2 * w    ) * FP + 2 * kp] = __byte_perm(b0, b1, 0x5410);
            *(unsigned*)&sVl[(2 * w + 1) * FP + 2 * kp] = __byte_perm(b0, b1, 0x7632);
        }
        __syncthreads();

        float sc[8][4];
        #pragma unroll
        for (int nf = 0; nf < 8; nf++)
            #pragma unroll
            for (int e = 0; e < 4; e++) sc[nf][e] = 0.f;

        #pragma unroll
        for (int kc = 0; kc < 4; kc++) {
            const int r0 = warp * 16 + g;
            const int kk = kc * 16 + tg * 2;
            unsigned qh[4], ql[4];
            qh[0] = *(const unsigned*)&sQh[(r0    ) * FP + kk    ];
            qh[1] = *(const unsigned*)&sQh[(r0 + 8) * FP + kk    ];
            qh[2] = *(const unsigned*)&sQh[(r0    ) * FP + kk + 8];
            qh[3] = *(const unsigned*)&sQh[(r0 + 8) * FP + kk + 8];
            ql[0] = *(const unsigned*)&sQl[(r0    ) * FP + kk    ];
            ql[1] = *(const unsigned*)&sQl[(r0 + 8) * FP + kk    ];
            ql[2] = *(const unsigned*)&sQl[(r0    ) * FP + kk + 8];
            ql[3] = *(const unsigned*)&sQl[(r0 + 8) * FP + kk + 8];
            #pragma unroll
            for (int nf = 0; nf < 8; nf++) {
                int n = nf * 8 + g;
                unsigned bh[2], bl[2];
                bh[0] = *(const unsigned*)&sKh[n * FP + kk    ];
                bh[1] = *(const unsigned*)&sKh[n * FP + kk + 8];
                bl[0] = *(const unsigned*)&sKl[n * FP + kk    ];
                bl[1] = *(const unsigned*)&sKl[n * FP + kk + 8];
                mma16816(sc[nf], qh, bh);
                mma16816(sc[nf], qh, bl);
                mma16816(sc[nf], ql, bh);
            }
        }

        const bool diag = (kb == qb);
        float rm0 = -1e30f, rm1 = -1e30f;
        #pragma unroll
        for (int nf = 0; nf < 8; nf++) {
            #pragma unroll
            for (int e = 0; e < 2; e++) {
                int kg = kb * 64 + nf * 8 + tg * 2 + e;
                float v0 = sc[nf][e] * scale;
                if (diag && kg > qrow0) v0 = -1e30f;
                sc[nf][e] = v0;
                rm0 = fmaxf(rm0, v0);
                float v1 = sc[nf][e + 2] * scale;
                if (diag && kg > qrow0 + 8) v1 = -1e30f;
                sc[nf][e + 2] = v1;
                rm1 = fmaxf(rm1, v1);
            }
        }
        rm0 = fmaxf(rm0, __shfl_xor_sync(0xffffffffu, rm0, 1));
        rm0 = fmaxf(rm0, __shfl_xor_sync(0xffffffffu, rm0, 2));
        rm1 = fmaxf(rm1, __shfl_xor_sync(0xffffffffu, rm1, 1));
        rm1 = fmaxf(rm1, __shfl_xor_sync(0xffffffffu, rm1, 2));

        const float mn0 = fmaxf(m0, rm0);
        const float mn1 = fmaxf(m1, rm1);
        const float a0 = exp2f((m0 - mn0) * LOG2E);
        const float a1 = exp2f((m1 - mn1) * LOG2E);
        m0 = mn0; m1 = mn1;
        l0 *= a0;  l1 *= a1;
        #pragma unroll
        for (int nf = 0; nf < 8; nf++) {
            oacc[nf][0] *= a0; oacc[nf][1] *= a0;
            oacc[nf][2] *= a1; oacc[nf][3] *= a1;
        }

        float rs0 = 0.f, rs1 = 0.f;
        #pragma unroll
        for (int nf = 0; nf < 8; nf++) {
            float p0 = exp2f((sc[nf][0] - mn0) * LOG2E);
            float p1 = exp2f((sc[nf][1] - mn0) * LOG2E);
            float p2 = exp2f((sc[nf][2] - mn1) * LOG2E);
            float p3 = exp2f((sc[nf][3] - mn1) * LOG2E);
            sc[nf][0] = p0; sc[nf][1] = p1; sc[nf][2] = p2; sc[nf][3] = p3;
            rs0 += p0 + p1; rs1 += p2 + p3;
        }
        rs0 += __shfl_xor_sync(0xffffffffu, rs0, 1);
        rs0 += __shfl_xor_sync(0xffffffffu, rs0, 2);
        rs1 += __shfl_xor_sync(0xffffffffu, rs1, 1);
        rs1 += __shfl_xor_sync(0xffffffffu, rs1, 2);
        l0 += rs0; l1 += rs1;

        unsigned ph[8][2], pl[8][2];
        #pragma unroll
        for (int nf = 0; nf < 8; nf++) {
            ph[nf][0] = pack2hi(sc[nf][0], sc[nf][1]);
            ph[nf][1] = pack2hi(sc[nf][2], sc[nf][3]);
            pl[nf][0] = pack2lo(sc[nf][0], sc[nf][1]);
            pl[nf][1] = pack2lo(sc[nf][2], sc[nf][3]);
        }

        #pragma unroll
        for (int kc = 0; kc < 4; kc++) {
            unsigned ah[4] = { ph[2*kc][0], ph[2*kc][1], ph[2*kc+1][0], ph[2*kc+1][1] };
            unsigned al[4] = { pl[2*kc][0], pl[2*kc][1], pl[2*kc+1][0], pl[2*kc+1][1] };
            const int kk = kc * 16 + tg * 2;
            #pragma unroll
            for (int nf = 0; nf < 8; nf++) {
                int n = nf * 8 + g;
                unsigned vh[2], vl[2];
                vh[0] = *(const unsigned*)&sVh[n * FP + kk    ];
                vh[1] = *(const unsigned*)&sVh[n * FP + kk + 8];
                vl[0] = *(const unsigned*)&sVl[n * FP + kk    ];
                vl[1] = *(const unsigned*)&sVl[n * FP + kk + 8];
                mma16816(oacc[nf], ah, vh);
                mma16816(oacc[nf], ah, vl);
                mma16816(oacc[nf], al, vh);
            }
        }
    }

    // ---- normalize + store fp16 for the O-projection ----
    const float inv0 = 1.0f / l0;
    const float inv1 = 1.0f / l1;
    const size_t rowbase = (size_t)(b * S_ + qb * 64);
    const int r0 = warp * 16 + g;
    #pragma unroll
    for (int nf = 0; nf < 8; nf++) {
        int c = head * DH_ + nf * 8 + tg * 2;
        *(unsigned*)&AO[(rowbase + r0    ) * QKDIM_ + c] =
            pack2half(oacc[nf][0] * inv0, oacc[nf][1] * inv0);
        *(unsigned*)&AO[(rowbase + r0 + 8) * QKDIM_ + c] =
            pack2half(oacc[nf][2] * inv1, oacc[nf][3] * inv1);
    }
}

// ---------------------------------------------------------------------------
extern "C" void kernel_launch(void* const* d_in, const int* in_sizes, int n_in,
                              void* d_out, int out_size)
{
    const float* X  = (const float*)d_in[0];
    const float* WQ = (const float*)d_in[1];
    const float* WK = (const float*)d_in[2];
    const float* WV = (const float*)d_in[3];
    const float* WO = (const float*)d_in[4];
    float* out = (float*)d_out;

    __half *xp, *wqp, *wkp, *wvp, *wop, *aop;
    bf16 *qh, *ql, *kh, *kl, *vh, *vl;
    cudaGetSymbolAddress((void**)&xp,  hX);
    cudaGetSymbolAddress((void**)&wqp, hWQ);
    cudaGetSymbolAddress((void**)&wkp, hWK);
    cudaGetSymbolAddress((void**)&wvp, hWV);
    cudaGetSymbolAddress((void**)&wop, hWOt);
    cudaGetSymbolAddress((void**)&aop, hAO);
    cudaGetSymbolAddress((void**)&qh,  sqh);  cudaGetSymbolAddress((void**)&ql,  sql);
    cudaGetSymbolAddress((void**)&kh,  skh);  cudaGetSymbolAddress((void**)&kl,  skl);
    cudaGetSymbolAddress((void**)&vh,  svh);  cudaGetSymbolAddress((void**)&vl,  svl);

    // ---- conversions (fp32 -> fp16 single) ----
    {
        int n4;
        n4 = BS_ * DM_ / 4;
        k_half<<<(n4 + 255) / 256, 256>>>((const float4*)X,  (uint2*)xp,  n4);
        n4 = QKDIM_ * DM_ / 4;
        k_half<<<(n4 + 255) / 256, 256>>>((const float4*)WQ, (uint2*)wqp, n4);
        n4 = KVDIM_ * DM_ / 4;
        k_half<<<(n4 + 255) / 256, 256>>>((const float4*)WK, (uint2*)wkp, n4);
        k_half<<<(n4 + 255) / 256, 256>>>((const float4*)WV, (uint2*)wvp, n4);
        k_half_t<<<dim3(DM_ / 32, QKDIM_ / 32), dim3(32, 8)>>>(WO, wop);
    }

    const int GEMM_SMEM = 2 * 2 * GSTAGE * 2;   // 40960 bytes
    cudaFuncSetAttribute(gemm_nt<1>, cudaFuncAttributeMaxDynamicSharedMemorySize, GEMM_SMEM);
    cudaFuncSetAttribute(gemm_nt<0>, cudaFuncAttributeMaxDynamicSharedMemorySize, GEMM_SMEM);
    cudaFuncSetAttribute(flash_mma,  cudaFuncAttributeMaxDynamicSharedMemorySize, FA_SMEM);

    // ---- QKV projections (fp16 single-product; bf16 split outputs for flash) ----
    gemm_nt<1><<<dim3(QKDIM_ / 128, BS_ / 128), 128, GEMM_SMEM>>>(
        xp, wqp, nullptr, qh, ql, BS_, QKDIM_, DM_);
    gemm_nt<1><<<dim3(KVDIM_ / 128, BS_ / 128), 128, GEMM_SMEM>>>(
        xp, wkp, nullptr, kh, kl, BS_, KVDIM_, DM_);
    gemm_nt<1><<<dim3(KVDIM_ / 128, BS_ / 128), 128, GEMM_SMEM>>>(
        xp, wvp, nullptr, vh, vl, BS_, KVDIM_, DM_);

    // ---- flash attention (bf16 split internals; fp16 output) ----
    flash_mma<<<dim3(S_ / 64, NH_, B_), 128, FA_SMEM>>>(qh, ql, kh, kl, vh, vl, aop);

    // ---- output projection (fp16 single-product, fp32 out) ----
    gemm_nt<0><<<dim3(DM_ / 128, BS_ / 128), 128, GEMM_SMEM>>>(
        aop, wop, out, nullptr, nullptr, BS_, DM_, DM_);
}